// round 1
// baseline (speedup 1.0000x reference)
#include <cuda_runtime.h>
#include <math.h>

// Problem constants (fixed by the dataset)
#define B_ 4
#define S_ 4096
#define E_ 2048
#define A_ 2048

// GEMM tiling
#define BM 128
#define BN 128
#define BK 8
#define NTHREADS 256

// Scratch (allocation-free rule: __device__ globals)
__device__ float g_Q[(size_t)B_ * S_ * A_];
__device__ float g_K[(size_t)B_ * S_ * A_];
__device__ float g_V[(size_t)B_ * S_ * A_];
__device__ float g_P[(size_t)B_ * S_ * S_];   // scores -> probs in place

#define NEG_INF (-1e30f)

// ---------------------------------------------------------------------------
// C[M,N] = X[M,K] * W[N,K]^T   (projection: M=B*S=16384, N=A=2048, K=E=2048)
// All dims divisible by tile sizes -> no bounds checks.
// ---------------------------------------------------------------------------
__global__ __launch_bounds__(NTHREADS, 2)
void proj_kernel(const float* __restrict__ X, const float* __restrict__ W,
                 float* __restrict__ Out) {
    __shared__ float As[BK][BM];
    __shared__ float Bs[BK][BN];

    const int bm = blockIdx.y * BM;
    const int bn = blockIdx.x * BN;
    const int tid = threadIdx.x;
    const int tx = tid & 15;       // 0..15 -> N
    const int ty = tid >> 4;       // 0..15 -> M

    // loaders: 128 rows x 8 cols, float4 along K
    const int ar = tid >> 1;
    const int ac = (tid & 1) * 4;

    float acc[8][8];
#pragma unroll
    for (int i = 0; i < 8; i++)
#pragma unroll
        for (int j = 0; j < 8; j++) acc[i][j] = 0.f;

    for (int k0 = 0; k0 < E_; k0 += BK) {
        float4 av = *(const float4*)&X[(size_t)(bm + ar) * E_ + k0 + ac];
        float4 bv = *(const float4*)&W[(size_t)(bn + ar) * E_ + k0 + ac];
        As[ac + 0][ar] = av.x; As[ac + 1][ar] = av.y;
        As[ac + 2][ar] = av.z; As[ac + 3][ar] = av.w;
        Bs[ac + 0][ar] = bv.x; Bs[ac + 1][ar] = bv.y;
        Bs[ac + 2][ar] = bv.z; Bs[ac + 3][ar] = bv.w;
        __syncthreads();
#pragma unroll
        for (int k = 0; k < BK; k++) {
            float a[8], b[8];
            *(float4*)&a[0] = *(const float4*)&As[k][ty * 8];
            *(float4*)&a[4] = *(const float4*)&As[k][ty * 8 + 4];
            *(float4*)&b[0] = *(const float4*)&Bs[k][tx * 8];
            *(float4*)&b[4] = *(const float4*)&Bs[k][tx * 8 + 4];
#pragma unroll
            for (int i = 0; i < 8; i++)
#pragma unroll
                for (int j = 0; j < 8; j++) acc[i][j] = fmaf(a[i], b[j], acc[i][j]);
        }
        __syncthreads();
    }

#pragma unroll
    for (int i = 0; i < 8; i++) {
        const size_t r = (size_t)(bm + ty * 8 + i) * A_ + bn + tx * 8;
        float4 v0 = make_float4(acc[i][0], acc[i][1], acc[i][2], acc[i][3]);
        float4 v1 = make_float4(acc[i][4], acc[i][5], acc[i][6], acc[i][7]);
        *(float4*)&Out[r] = v0;
        *(float4*)&Out[r + 4] = v1;
    }
}

// ---------------------------------------------------------------------------
// scores[b,q,k] = (Q[b,q,:] . K[b,k,:]) / sqrt(A), causal mask -> g_P
// ---------------------------------------------------------------------------
__global__ __launch_bounds__(NTHREADS, 2)
void scores_kernel() {
    const int b  = blockIdx.z;
    const int qm = blockIdx.y * BM;    // query tile start
    const int kn = blockIdx.x * BN;    // key tile start
    const int tid = threadIdx.x;
    const int tx = tid & 15;
    const int ty = tid >> 4;

    float* __restrict__ Cp = g_P + (size_t)b * S_ * S_;

    if (kn > qm + BM - 1) {
        // fully masked tile: fill with -inf surrogate
        const float4 neg = make_float4(NEG_INF, NEG_INF, NEG_INF, NEG_INF);
#pragma unroll
        for (int i = 0; i < 8; i++) {
            const size_t r = (size_t)(qm + ty * 8 + i) * S_ + kn + tx * 8;
            *(float4*)&Cp[r] = neg;
            *(float4*)&Cp[r + 4] = neg;
        }
        return;
    }

    const float* __restrict__ Qp = g_Q + (size_t)b * S_ * A_;
    const float* __restrict__ Kp = g_K + (size_t)b * S_ * A_;

    __shared__ float As[BK][BM];
    __shared__ float Bs[BK][BN];
    const int ar = tid >> 1;
    const int ac = (tid & 1) * 4;

    float acc[8][8];
#pragma unroll
    for (int i = 0; i < 8; i++)
#pragma unroll
        for (int j = 0; j < 8; j++) acc[i][j] = 0.f;

    for (int k0 = 0; k0 < A_; k0 += BK) {
        float4 av = *(const float4*)&Qp[(size_t)(qm + ar) * A_ + k0 + ac];
        float4 bv = *(const float4*)&Kp[(size_t)(kn + ar) * A_ + k0 + ac];
        As[ac + 0][ar] = av.x; As[ac + 1][ar] = av.y;
        As[ac + 2][ar] = av.z; As[ac + 3][ar] = av.w;
        Bs[ac + 0][ar] = bv.x; Bs[ac + 1][ar] = bv.y;
        Bs[ac + 2][ar] = bv.z; Bs[ac + 3][ar] = bv.w;
        __syncthreads();
#pragma unroll
        for (int k = 0; k < BK; k++) {
            float a[8], b2[8];
            *(float4*)&a[0] = *(const float4*)&As[k][ty * 8];
            *(float4*)&a[4] = *(const float4*)&As[k][ty * 8 + 4];
            *(float4*)&b2[0] = *(const float4*)&Bs[k][tx * 8];
            *(float4*)&b2[4] = *(const float4*)&Bs[k][tx * 8 + 4];
#pragma unroll
            for (int i = 0; i < 8; i++)
#pragma unroll
                for (int j = 0; j < 8; j++) acc[i][j] = fmaf(a[i], b2[j], acc[i][j]);
        }
        __syncthreads();
    }

    const float scale = rsqrtf((float)A_);
#pragma unroll
    for (int i = 0; i < 8; i++) {
        const int q = qm + ty * 8 + i;
#pragma unroll
        for (int j = 0; j < 8; j++) {
            const int kk = kn + tx * 8 + j;
            Cp[(size_t)q * S_ + kk] = (kk <= q) ? acc[i][j] * scale : NEG_INF;
        }
    }
}

// ---------------------------------------------------------------------------
// row-wise softmax over g_P (16384 rows of 4096). Masked entries are -1e30.
// ---------------------------------------------------------------------------
__global__ __launch_bounds__(256)
void softmax_kernel() {
    const size_t row = blockIdx.x;
    float* __restrict__ p = g_P + row * S_;
    const int tid = threadIdx.x;

    __shared__ float red[8];

    // max
    float m = NEG_INF;
    for (int i = tid; i < S_; i += 256) m = fmaxf(m, p[i]);
#pragma unroll
    for (int o = 16; o > 0; o >>= 1) m = fmaxf(m, __shfl_xor_sync(0xffffffff, m, o));
    if ((tid & 31) == 0) red[tid >> 5] = m;
    __syncthreads();
    if (tid < 32) {
        float v = (tid < 8) ? red[tid] : NEG_INF;
#pragma unroll
        for (int o = 4; o > 0; o >>= 1) v = fmaxf(v, __shfl_xor_sync(0xffffffff, v, o));
        if (tid == 0) red[0] = v;
    }
    __syncthreads();
    const float M = red[0];
    __syncthreads();

    // exp + sum
    float s = 0.f;
    for (int i = tid; i < S_; i += 256) {
        float e = __expf(p[i] - M);
        p[i] = e;
        s += e;
    }
#pragma unroll
    for (int o = 16; o > 0; o >>= 1) s += __shfl_xor_sync(0xffffffff, s, o);
    if ((tid & 31) == 0) red[tid >> 5] = s;
    __syncthreads();
    if (tid < 32) {
        float v = (tid < 8) ? red[tid] : 0.f;
#pragma unroll
        for (int o = 4; o > 0; o >>= 1) v += __shfl_xor_sync(0xffffffff, v, o);
        if (tid == 0) red[0] = v;
    }
    __syncthreads();
    const float inv = 1.f / red[0];

    for (int i = tid; i < S_; i += 256) p[i] *= inv;
}

// ---------------------------------------------------------------------------
// out[b,q,a] = sum_k P[b,q,k] * V[b,k,a]   (NN GEMM, causal k-limit)
// final rounding to 4 decimals (round-half-even, matching jnp.round)
// ---------------------------------------------------------------------------
__global__ __launch_bounds__(NTHREADS, 2)
void pv_kernel(float* __restrict__ Out) {
    const int b  = blockIdx.z;
    const int bm = blockIdx.y * BM;    // q tile
    const int bn = blockIdx.x * BN;    // a tile
    const int tid = threadIdx.x;
    const int tx = tid & 15;
    const int ty = tid >> 4;

    const float* __restrict__ Pp = g_P + (size_t)b * S_ * S_;
    const float* __restrict__ Vp = g_V + (size_t)b * S_ * A_;
    float* __restrict__ Op = Out + (size_t)b * S_ * A_;

    __shared__ float As[BK][BM];
    __shared__ float Bs[BK][BN];

    // A (=P) loader: 128 rows x 8 cols, K-contiguous
    const int ar = tid >> 1;
    const int ac = (tid & 1) * 4;
    // B (=V) loader: 8 rows x 128 cols, N-contiguous
    const int br = tid >> 5;
    const int bc = (tid & 31) * 4;

    float acc[8][8];
#pragma unroll
    for (int i = 0; i < 8; i++)
#pragma unroll
        for (int j = 0; j < 8; j++) acc[i][j] = 0.f;

    const int kend = bm + BM;   // causal: rows in [bm, bm+127] have k <= q < bm+128
    for (int k0 = 0; k0 < kend; k0 += BK) {
        float4 av = *(const float4*)&Pp[(size_t)(bm + ar) * S_ + k0 + ac];
        float4 bv = *(const float4*)&Vp[(size_t)(k0 + br) * A_ + bn + bc];
        As[ac + 0][ar] = av.x; As[ac + 1][ar] = av.y;
        As[ac + 2][ar] = av.z; As[ac + 3][ar] = av.w;
        *(float4*)&Bs[br][bc] = bv;
        __syncthreads();
#pragma unroll
        for (int k = 0; k < BK; k++) {
            float a[8], b2[8];
            *(float4*)&a[0] = *(const float4*)&As[k][ty * 8];
            *(float4*)&a[4] = *(const float4*)&As[k][ty * 8 + 4];
            *(float4*)&b2[0] = *(const float4*)&Bs[k][tx * 8];
            *(float4*)&b2[4] = *(const float4*)&Bs[k][tx * 8 + 4];
#pragma unroll
            for (int i = 0; i < 8; i++)
#pragma unroll
                for (int j = 0; j < 8; j++) acc[i][j] = fmaf(a[i], b2[j], acc[i][j]);
        }
        __syncthreads();
    }

#pragma unroll
    for (int i = 0; i < 8; i++) {
        const size_t r = (size_t)(bm + ty * 8 + i) * A_ + bn + tx * 8;
        float4 v0, v1;
        v0.x = rintf(acc[i][0] * 1e4f) * 1e-4f;
        v0.y = rintf(acc[i][1] * 1e4f) * 1e-4f;
        v0.z = rintf(acc[i][2] * 1e4f) * 1e-4f;
        v0.w = rintf(acc[i][3] * 1e4f) * 1e-4f;
        v1.x = rintf(acc[i][4] * 1e4f) * 1e-4f;
        v1.y = rintf(acc[i][5] * 1e4f) * 1e-4f;
        v1.z = rintf(acc[i][6] * 1e4f) * 1e-4f;
        v1.w = rintf(acc[i][7] * 1e4f) * 1e-4f;
        *(float4*)&Op[r] = v0;
        *(float4*)&Op[r + 4] = v1;
    }
}

// ---------------------------------------------------------------------------
extern "C" void kernel_launch(void* const* d_in, const int* in_sizes, int n_in,
                              void* d_out, int out_size) {
    const float* x  = (const float*)d_in[0];   // embedded [B,S,E]
    const float* Wk = (const float*)d_in[1];   // [A,E]
    const float* Wq = (const float*)d_in[2];   // [A,E]
    const float* Wv = (const float*)d_in[3];   // [A,E]
    float* out = (float*)d_out;                // [B,S,A]

    float *dQ, *dK, *dV;
    cudaGetSymbolAddress((void**)&dQ, g_Q);
    cudaGetSymbolAddress((void**)&dK, g_K);
    cudaGetSymbolAddress((void**)&dV, g_V);

    dim3 thr(NTHREADS);

    // Projections: M = B*S = 16384, N = A = 2048
    dim3 gproj(A_ / BN, (B_ * S_) / BM);
    proj_kernel<<<gproj, thr>>>(x, Wq, dQ);
    proj_kernel<<<gproj, thr>>>(x, Wk, dK);
    proj_kernel<<<gproj, thr>>>(x, Wv, dV);

    // Scores (causal): per batch S x S
    dim3 gsc(S_ / BN, S_ / BM, B_);
    scores_kernel<<<gsc, thr>>>();

    // Softmax: one block per row
    softmax_kernel<<<B_ * S_, 256>>>();

    // P @ V
    dim3 gpv(A_ / BN, S_ / BM, B_);
    pv_kernel<<<gpv, thr>>>(out);
}

// round 2
// speedup vs baseline: 1.4596x; 1.4596x over previous
#include <cuda_runtime.h>
#include <math.h>
#include <stdint.h>

// Problem constants (fixed by the dataset)
#define B_ 4
#define S_ 4096
#define E_ 2048
#define A_ 2048

// GEMM tiling
#define BM 128
#define BN 128
#define BK 16
#define NTHREADS 256
#define AS_ (BM + 4)   // smem row stride (floats); keeps float4 alignment, skews banks
#define BS_ (BN + 4)

#define NEG_INF (-1e30f)

// Scratch (allocation-free rule: __device__ globals)
__device__ float g_Q[(size_t)B_ * S_ * A_];
__device__ float g_K[(size_t)B_ * S_ * A_];
__device__ float g_V[(size_t)B_ * S_ * A_];
__device__ float g_P[(size_t)B_ * S_ * S_];   // scores -> probs in place

// ---------------------------------------------------------------------------
// helpers
// ---------------------------------------------------------------------------
__device__ __forceinline__ uint32_t f2tf(float x) {
    uint32_t r;
    asm("cvt.rna.tf32.f32 %0, %1;" : "=r"(r) : "f"(x));
    return r;
}
__device__ __forceinline__ float u2f(uint32_t x) { return __uint_as_float(x); }

#define MMA_TF32(C, Af, Bf)                                                   \
    asm volatile(                                                             \
        "mma.sync.aligned.m16n8k8.row.col.f32.tf32.tf32.f32 "                 \
        "{%0,%1,%2,%3}, {%4,%5,%6,%7}, {%8,%9}, {%0,%1,%2,%3};"               \
        : "+f"((C)[0]), "+f"((C)[1]), "+f"((C)[2]), "+f"((C)[3])              \
        : "r"((Af)[0]), "r"((Af)[1]), "r"((Af)[2]), "r"((Af)[3]),             \
          "r"((Bf)[0]), "r"((Bf)[1]))

// Load a 128x16 tile from row-major G (row stride ld), rows row0..row0+127,
// cols k0..k0+15, into two float4 regs per thread.
__device__ __forceinline__ void ldg_tileT(const float* __restrict__ G, size_t ld,
                                          int row0, int k0, int tid,
                                          float4& v0, float4& v1) {
    const int m0 = tid >> 2;
    const int kc = (tid & 3) * 4;
    v0 = *(const float4*)(G + (size_t)(row0 + m0) * ld + k0 + kc);
    v1 = *(const float4*)(G + (size_t)(row0 + 64 + m0) * ld + k0 + kc);
}
// Store the regs into S[k][m] layout (transpose), converting to tf32.
__device__ __forceinline__ void sts_tileT(float* S, int tid, float4 v0, float4 v1) {
    const int m0 = tid >> 2;
    const int kc = (tid & 3) * 4;
    S[(kc + 0) * AS_ + m0] = u2f(f2tf(v0.x));
    S[(kc + 1) * AS_ + m0] = u2f(f2tf(v0.y));
    S[(kc + 2) * AS_ + m0] = u2f(f2tf(v0.z));
    S[(kc + 3) * AS_ + m0] = u2f(f2tf(v0.w));
    S[(kc + 0) * AS_ + 64 + m0] = u2f(f2tf(v1.x));
    S[(kc + 1) * AS_ + 64 + m0] = u2f(f2tf(v1.y));
    S[(kc + 2) * AS_ + 64 + m0] = u2f(f2tf(v1.z));
    S[(kc + 3) * AS_ + 64 + m0] = u2f(f2tf(v1.w));
}

// Load a 16x128 tile from row-major G (row stride ld), rows k0..k0+15,
// cols n0..n0+127 (n-contiguous), two float4 per thread.
__device__ __forceinline__ void ldg_tileD(const float* __restrict__ G, size_t ld,
                                          int k0, int n0, int tid,
                                          float4& v0, float4& v1) {
    const int k  = tid >> 5;          // 0..7
    const int n4 = (tid & 31) * 4;    // 0..124
    v0 = *(const float4*)(G + (size_t)(k0 + k) * ld + n0 + n4);
    v1 = *(const float4*)(G + (size_t)(k0 + 8 + k) * ld + n0 + n4);
}
__device__ __forceinline__ void sts_tileD(float* S, int tid, float4 v0, float4 v1) {
    const int k  = tid >> 5;
    const int n4 = (tid & 31) * 4;
    float4 w0 = make_float4(u2f(f2tf(v0.x)), u2f(f2tf(v0.y)),
                            u2f(f2tf(v0.z)), u2f(f2tf(v0.w)));
    float4 w1 = make_float4(u2f(f2tf(v1.x)), u2f(f2tf(v1.y)),
                            u2f(f2tf(v1.z)), u2f(f2tf(v1.w)));
    *(float4*)(S + (size_t)k * BS_ + n4)       = w0;
    *(float4*)(S + (size_t)(k + 8) * BS_ + n4) = w1;
}

// One BK slab of tensor-core work: 16 m16n8k8 mmas per warp per 8-k substep.
__device__ __forceinline__ void mma_compute(const float* As0, const float* Bs0,
                                            int wm, int wn, int lr, int lc,
                                            float c[4][4][4]) {
#pragma unroll
    for (int kk = 0; kk < BK; kk += 8) {
        uint32_t a[4][4], b[4][2];
#pragma unroll
        for (int i = 0; i < 4; i++) {
            const float* p0 = As0 + (kk + lc) * AS_ + wm + 16 * i + lr;
            const float* p1 = As0 + (kk + lc + 4) * AS_ + wm + 16 * i + lr;
            a[i][0] = __float_as_uint(p0[0]);
            a[i][1] = __float_as_uint(p0[8]);
            a[i][2] = __float_as_uint(p1[0]);
            a[i][3] = __float_as_uint(p1[8]);
        }
#pragma unroll
        for (int j = 0; j < 4; j++) {
            b[j][0] = __float_as_uint(Bs0[(kk + lc) * BS_ + wn + 8 * j + lr]);
            b[j][1] = __float_as_uint(Bs0[(kk + lc + 4) * BS_ + wn + 8 * j + lr]);
        }
#pragma unroll
        for (int i = 0; i < 4; i++)
#pragma unroll
            for (int j = 0; j < 4; j++) MMA_TF32(c[i][j], a[i], b[j]);
    }
}

// ---------------------------------------------------------------------------
// Projection: Out[M,N] = X[M,K] * W[N,K]^T   (M=16384, N=2048, K=2048)
// ---------------------------------------------------------------------------
__global__ __launch_bounds__(NTHREADS, 1)
void proj_tc(const float* __restrict__ X, const float* __restrict__ W,
             float* __restrict__ Out) {
    __shared__ float As[2][BK * AS_];
    __shared__ float Bs[2][BK * BS_];
    const int tid = threadIdx.x, lane = tid & 31, warp = tid >> 5;
    const int lr = lane >> 2, lc = lane & 3;
    const int wm = (warp >> 2) * 64, wn = (warp & 3) * 32;
    const int bm = blockIdx.y * BM, bn = blockIdx.x * BN;

    float c[4][4][4] = {};

    float4 a0, a1, b0, b1;
    ldg_tileT(X, E_, bm, 0, tid, a0, a1);
    ldg_tileT(W, E_, bn, 0, tid, b0, b1);
    sts_tileT(As[0], tid, a0, a1);
    sts_tileT(Bs[0], tid, b0, b1);
    __syncthreads();

    int buf = 0;
    for (int k0 = BK; k0 < E_; k0 += BK) {
        ldg_tileT(X, E_, bm, k0, tid, a0, a1);
        ldg_tileT(W, E_, bn, k0, tid, b0, b1);
        mma_compute(As[buf], Bs[buf], wm, wn, lr, lc, c);
        sts_tileT(As[buf ^ 1], tid, a0, a1);
        sts_tileT(Bs[buf ^ 1], tid, b0, b1);
        __syncthreads();
        buf ^= 1;
    }
    mma_compute(As[buf], Bs[buf], wm, wn, lr, lc, c);

#pragma unroll
    for (int i = 0; i < 4; i++)
#pragma unroll
        for (int j = 0; j < 4; j++) {
            const int r0 = bm + wm + 16 * i + lr;
            const int cc = bn + wn + 8 * j + 2 * lc;
            *(float2*)&Out[(size_t)r0 * A_ + cc] = make_float2(c[i][j][0], c[i][j][1]);
            *(float2*)&Out[(size_t)(r0 + 8) * A_ + cc] = make_float2(c[i][j][2], c[i][j][3]);
        }
}

// ---------------------------------------------------------------------------
// scores[b,q,k] = (Q[b,q,:] . K[b,k,:]) / sqrt(A), causal mask -> g_P
// ---------------------------------------------------------------------------
__global__ __launch_bounds__(NTHREADS, 1)
void scores_tc() {
    const int b  = blockIdx.z;
    const int qm = blockIdx.y * BM;
    const int kn = blockIdx.x * BN;
    const int tid = threadIdx.x;

    float* __restrict__ Cp = g_P + (size_t)b * S_ * S_;

    if (kn >= qm + BM) {
        // fully masked tile
        const float4 neg = make_float4(NEG_INF, NEG_INF, NEG_INF, NEG_INF);
#pragma unroll
        for (int t = 0; t < 16; t++) {
            const int v = tid + t * 256;          // 4096 float4s
            const int m = v >> 5, n4 = (v & 31) * 4;
            *(float4*)&Cp[(size_t)(qm + m) * S_ + kn + n4] = neg;
        }
        return;
    }

    const float* __restrict__ Qp = g_Q + (size_t)b * S_ * A_;
    const float* __restrict__ Kp = g_K + (size_t)b * S_ * A_;

    __shared__ float As[2][BK * AS_];
    __shared__ float Bs[2][BK * BS_];
    const int lane = tid & 31, warp = tid >> 5;
    const int lr = lane >> 2, lc = lane & 3;
    const int wm = (warp >> 2) * 64, wn = (warp & 3) * 32;

    float c[4][4][4] = {};

    float4 a0, a1, b0, b1;
    ldg_tileT(Qp, A_, qm, 0, tid, a0, a1);
    ldg_tileT(Kp, A_, kn, 0, tid, b0, b1);
    sts_tileT(As[0], tid, a0, a1);
    sts_tileT(Bs[0], tid, b0, b1);
    __syncthreads();

    int buf = 0;
    for (int k0 = BK; k0 < A_; k0 += BK) {
        ldg_tileT(Qp, A_, qm, k0, tid, a0, a1);
        ldg_tileT(Kp, A_, kn, k0, tid, b0, b1);
        mma_compute(As[buf], Bs[buf], wm, wn, lr, lc, c);
        sts_tileT(As[buf ^ 1], tid, a0, a1);
        sts_tileT(Bs[buf ^ 1], tid, b0, b1);
        __syncthreads();
        buf ^= 1;
    }
    mma_compute(As[buf], Bs[buf], wm, wn, lr, lc, c);

    const float scale = rsqrtf((float)A_);
#pragma unroll
    for (int i = 0; i < 4; i++)
#pragma unroll
        for (int j = 0; j < 4; j++) {
            const int q0 = qm + wm + 16 * i + lr;
            const int k0 = kn + wn + 8 * j + 2 * lc;
#pragma unroll
            for (int rr = 0; rr < 2; rr++) {
                const int q = q0 + rr * 8;
                float v0 = (k0     <= q) ? c[i][j][rr * 2 + 0] * scale : NEG_INF;
                float v1 = (k0 + 1 <= q) ? c[i][j][rr * 2 + 1] * scale : NEG_INF;
                *(float2*)&Cp[(size_t)q * S_ + k0] = make_float2(v0, v1);
            }
        }
}

// ---------------------------------------------------------------------------
// row-wise softmax over g_P (16384 rows of 4096). Masked entries are -1e30.
// ---------------------------------------------------------------------------
__global__ __launch_bounds__(256)
void softmax_kernel() {
    const size_t row = blockIdx.x;
    float* __restrict__ p = g_P + row * S_;
    const int tid = threadIdx.x;

    __shared__ float red[8];

    float m = NEG_INF;
    for (int i = tid; i < S_; i += 256) m = fmaxf(m, p[i]);
#pragma unroll
    for (int o = 16; o > 0; o >>= 1) m = fmaxf(m, __shfl_xor_sync(0xffffffff, m, o));
    if ((tid & 31) == 0) red[tid >> 5] = m;
    __syncthreads();
    if (tid < 32) {
        float v = (tid < 8) ? red[tid] : NEG_INF;
#pragma unroll
        for (int o = 4; o > 0; o >>= 1) v = fmaxf(v, __shfl_xor_sync(0xffffffff, v, o));
        if (tid == 0) red[0] = v;
    }
    __syncthreads();
    const float M = red[0];
    __syncthreads();

    float s = 0.f;
    for (int i = tid; i < S_; i += 256) {
        float e = __expf(p[i] - M);
        p[i] = e;
        s += e;
    }
#pragma unroll
    for (int o = 16; o > 0; o >>= 1) s += __shfl_xor_sync(0xffffffff, s, o);
    if ((tid & 31) == 0) red[tid >> 5] = s;
    __syncthreads();
    if (tid < 32) {
        float v = (tid < 8) ? red[tid] : 0.f;
#pragma unroll
        for (int o = 4; o > 0; o >>= 1) v += __shfl_xor_sync(0xffffffff, v, o);
        if (tid == 0) red[0] = v;
    }
    __syncthreads();
    const float inv = 1.f / red[0];

    for (int i = tid; i < S_; i += 256) p[i] *= inv;
}

// ---------------------------------------------------------------------------
// out[b,q,a] = sum_k P[b,q,k] * V[b,k,a]   (causal k-limit), round to 4 dp
// ---------------------------------------------------------------------------
__global__ __launch_bounds__(NTHREADS, 1)
void pv_tc(float* __restrict__ Out) {
    const int b  = blockIdx.z;
    const int bm = blockIdx.y * BM;   // q tile
    const int bn = blockIdx.x * BN;   // a tile
    const int tid = threadIdx.x, lane = tid & 31, warp = tid >> 5;
    const int lr = lane >> 2, lc = lane & 3;
    const int wm = (warp >> 2) * 64, wn = (warp & 3) * 32;

    const float* __restrict__ Pp = g_P + (size_t)b * S_ * S_;
    const float* __restrict__ Vp = g_V + (size_t)b * S_ * A_;
    float* __restrict__ Op = Out + (size_t)b * S_ * A_;

    __shared__ float As[2][BK * AS_];
    __shared__ float Bs[2][BK * BS_];

    float c[4][4][4] = {};

    const int kend = bm + BM;   // causal limit

    float4 a0, a1, b0, b1;
    ldg_tileT(Pp, S_, bm, 0, tid, a0, a1);
    ldg_tileD(Vp, A_, 0, bn, tid, b0, b1);
    sts_tileT(As[0], tid, a0, a1);
    sts_tileD(Bs[0], tid, b0, b1);
    __syncthreads();

    int buf = 0;
    for (int k0 = BK; k0 < kend; k0 += BK) {
        ldg_tileT(Pp, S_, bm, k0, tid, a0, a1);
        ldg_tileD(Vp, A_, k0, bn, tid, b0, b1);
        mma_compute(As[buf], Bs[buf], wm, wn, lr, lc, c);
        sts_tileT(As[buf ^ 1], tid, a0, a1);
        sts_tileD(Bs[buf ^ 1], tid, b0, b1);
        __syncthreads();
        buf ^= 1;
    }
    mma_compute(As[buf], Bs[buf], wm, wn, lr, lc, c);

#pragma unroll
    for (int i = 0; i < 4; i++)
#pragma unroll
        for (int j = 0; j < 4; j++) {
            const int r0 = bm + wm + 16 * i + lr;
            const int cc = bn + wn + 8 * j + 2 * lc;
            float2 v0, v1;
            v0.x = rintf(c[i][j][0] * 1e4f) * 1e-4f;
            v0.y = rintf(c[i][j][1] * 1e4f) * 1e-4f;
            v1.x = rintf(c[i][j][2] * 1e4f) * 1e-4f;
            v1.y = rintf(c[i][j][3] * 1e4f) * 1e-4f;
            *(float2*)&Op[(size_t)r0 * A_ + cc] = v0;
            *(float2*)&Op[(size_t)(r0 + 8) * A_ + cc] = v1;
        }
}

// ---------------------------------------------------------------------------
extern "C" void kernel_launch(void* const* d_in, const int* in_sizes, int n_in,
                              void* d_out, int out_size) {
    const float* x  = (const float*)d_in[0];   // embedded [B,S,E]
    const float* Wk = (const float*)d_in[1];   // [A,E]
    const float* Wq = (const float*)d_in[2];   // [A,E]
    const float* Wv = (const float*)d_in[3];   // [A,E]
    float* out = (float*)d_out;                // [B,S,A]

    float *dQ, *dK, *dV;
    cudaGetSymbolAddress((void**)&dQ, g_Q);
    cudaGetSymbolAddress((void**)&dK, g_K);
    cudaGetSymbolAddress((void**)&dV, g_V);

    dim3 thr(NTHREADS);

    // Projections: M = B*S = 16384, N = A = 2048
    dim3 gproj(A_ / BN, (B_ * S_) / BM);
    proj_tc<<<gproj, thr>>>(x, Wq, dQ);
    proj_tc<<<gproj, thr>>>(x, Wk, dK);
    proj_tc<<<gproj, thr>>>(x, Wv, dV);

    // Scores (causal): per batch S x S
    dim3 gsc(S_ / BN, S_ / BM, B_);
    scores_tc<<<gsc, thr>>>();

    // Softmax: one block per row
    softmax_kernel<<<B_ * S_, 256>>>();

    // P @ V
    dim3 gpv(A_ / BN, S_ / BM, B_);
    pv_tc<<<gpv, thr>>>(out);
}

// round 5
// speedup vs baseline: 3.5251x; 2.4151x over previous
#include <cuda_runtime.h>
#include <math.h>
#include <stdint.h>

// Problem constants
#define B_ 4
#define S_ 4096
#define E_ 2048
#define A_ 2048

// GEMM tiling (legacy mma.sync tf32 path; tcgen05 PTX features are not
// available because the harness PTX target is sm_103, not sm_103a)
#define TM 128
#define TN 128
#define BK 16
#define STAGES 3
#define NTH 256

#define ASR 20          // A smem row stride (floats): 16 data + 4 pad, 16B-aligned rows
#define BSR 20          // B K-major smem row stride
#define BNR 136         // B N-major smem row stride (PV): 544B, 16B-aligned
#define A_TILE_BYTES (TM * ASR * 4)            // 10240
#define B_TILE_BYTES (TM * BSR * 4)            // 10240 (>= 16*BNR*4 = 8704)
#define STAGE_BYTES (A_TILE_BYTES + B_TILE_BYTES)
#define SMEM_DYN (STAGES * STAGE_BYTES)        // 61440

#define NEG_INF (-1e30f)

// Scratch (allocation-free rule: __device__ globals)
__device__ float g_X [(size_t)B_ * S_ * E_];
__device__ float g_Wq[(size_t)A_ * E_];
__device__ float g_Wk[(size_t)A_ * E_];
__device__ float g_Wv[(size_t)A_ * E_];
__device__ float g_Q [(size_t)B_ * S_ * A_];
__device__ float g_K [(size_t)B_ * S_ * A_];
__device__ float g_V [(size_t)B_ * S_ * A_];
__device__ float g_P [(size_t)B_ * S_ * S_];

// ---------------------------------------------------------------------------
// helpers
// ---------------------------------------------------------------------------
__device__ __forceinline__ uint32_t f2tf(float x) {
    uint32_t r; asm("cvt.rna.tf32.f32 %0, %1;" : "=r"(r) : "f"(x)); return r;
}
__device__ __forceinline__ float rnd_tf(float x) { return __uint_as_float(f2tf(x)); }
__device__ __forceinline__ uint32_t s2u(const void* p) {
    uint32_t a;
    asm("{ .reg .u64 t; cvta.to.shared.u64 t, %1; cvt.u32.u64 %0, t; }" : "=r"(a) : "l"(p));
    return a;
}

#define CP16(sm, g) \
    asm volatile("cp.async.cg.shared.global [%0], [%1], 16;" :: "r"(sm), "l"(g) : "memory")
#define CP_COMMIT() asm volatile("cp.async.commit_group;" ::: "memory")
#define CP_WAIT1()  asm volatile("cp.async.wait_group 1;" ::: "memory")

#define MMA_TF32(C, Af, Bf)                                                   \
    asm volatile(                                                             \
        "mma.sync.aligned.m16n8k8.row.col.f32.tf32.tf32.f32 "                 \
        "{%0,%1,%2,%3}, {%4,%5,%6,%7}, {%8,%9}, {%0,%1,%2,%3};"               \
        : "+f"((C)[0]), "+f"((C)[1]), "+f"((C)[2]), "+f"((C)[3])              \
        : "r"((Af)[0]), "r"((Af)[1]), "r"((Af)[2]), "r"((Af)[3]),             \
          "r"((Bf)[0]), "r"((Bf)[1]))

// ---------------------------------------------------------------------------
// one BK=16 slab of mma work. BLAY: 0 = B K-major [n][k], 1 = B N-major [k][n]
// ---------------------------------------------------------------------------
template <int BLAY>
__device__ __forceinline__ void mma_stage(const float* __restrict__ As,
                                          const float* __restrict__ Bs,
                                          int wm, int wn, int lr, int lc,
                                          float c[4][4][4]) {
#pragma unroll
    for (int kk = 0; kk < BK; kk += 8) {
        uint32_t a[4][4], b[4][2];
#pragma unroll
        for (int i = 0; i < 4; i++) {
            const float* p = As + (wm + 16 * i + lr) * ASR + kk + lc;
            a[i][0] = __float_as_uint(p[0]);
            a[i][1] = __float_as_uint(p[8 * ASR]);
            a[i][2] = __float_as_uint(p[4]);
            a[i][3] = __float_as_uint(p[8 * ASR + 4]);
        }
#pragma unroll
        for (int j = 0; j < 4; j++) {
            if (BLAY == 0) {
                const float* p = Bs + (wn + 8 * j + lr) * BSR + kk + lc;
                b[j][0] = __float_as_uint(p[0]);
                b[j][1] = __float_as_uint(p[4]);
            } else {
                const float* p = Bs + (kk + lc) * BNR + wn + 8 * j + lr;
                b[j][0] = __float_as_uint(p[0]);
                b[j][1] = __float_as_uint(p[4 * BNR]);
            }
        }
#pragma unroll
        for (int i = 0; i < 4; i++)
#pragma unroll
            for (int j = 0; j < 4; j++) MMA_TF32(c[i][j], a[i], b[j]);
    }
}

// ---------------------------------------------------------------------------
// unified GEMM. EPI: 0 = projection (round-to-tf32 output),
//                1 = scores (scale + causal mask), 2 = PV (round to 4 dp)
// A always [M][K] row-major (K-major); B: EPI<2 -> [N][K], EPI==2 -> [K][N]
// ---------------------------------------------------------------------------
template <int EPI>
__global__ void __launch_bounds__(NTH, 2)
gemm_tc(const float* __restrict__ Ab, const float* __restrict__ Bb,
        float* __restrict__ Cb) {
    const int bz = blockIdx.z;
    const int qm = blockIdx.y * TM;
    const int bn = blockIdx.x * TN;

    if (EPI == 1 && bn >= qm + TM) return;   // fully masked score tile: skip

    const float* Ap; const float* Bp; float* Cp;
    int lda, ldb, kch;
    if (EPI == 0) {
        Ap = Ab; Bp = Bb; Cp = Cb;
        lda = E_; ldb = E_; kch = E_ / BK;
    } else if (EPI == 1) {
        Ap = Ab + (size_t)bz * S_ * A_;
        Bp = Bb + (size_t)bz * S_ * A_;
        Cp = Cb + (size_t)bz * S_ * S_;
        lda = A_; ldb = A_; kch = A_ / BK;
    } else {
        Ap = Ab + (size_t)bz * S_ * S_;
        Bp = Bb + (size_t)bz * S_ * A_;
        Cp = Cb + (size_t)bz * S_ * A_;
        lda = S_; ldb = A_; kch = (qm + TM) / BK;   // causal K truncation
    }

    extern __shared__ char smraw[];
    const uint32_t sb = s2u(smraw);
    const int tid = threadIdx.x, lane = tid & 31, warp = tid >> 5;
    const int lr = lane >> 2, lc = lane & 3;
    const int wm = (warp >> 2) * 64, wn = (warp & 3) * 32;

    const float* Arow = Ap + (size_t)qm * lda;

    // ---- async loaders ----
    auto issue = [&](int it) {
        const uint32_t base = sb + (it % STAGES) * STAGE_BYTES;
        const int k0 = it * BK;
        // A tile: 128 rows x 4 chunks of 16B
        {
            int id = tid;                 // chunk 0
            int r = id >> 1, c = (id & 1) * 2;   // 2 chunks per thread id? no:
        }
        // A: 512 chunks, ids tid and tid+256
#pragma unroll
        for (int h = 0; h < 2; h++) {
            const int id = tid + h * NTH;
            const int r = id >> 2, c = id & 3;
            CP16(base + r * (ASR * 4) + c * 16,
                 Arow + (size_t)r * lda + k0 + c * 4);
        }
        // B: 512 chunks
        if (EPI < 2) {
#pragma unroll
            for (int h = 0; h < 2; h++) {
                const int id = tid + h * NTH;
                const int r = id >> 2, c = id & 3;
                CP16(base + A_TILE_BYTES + r * (BSR * 4) + c * 16,
                     Bp + (size_t)(bn + r) * ldb + k0 + c * 4);
            }
        } else {
#pragma unroll
            for (int h = 0; h < 2; h++) {
                const int id = tid + h * NTH;
                const int r = id >> 5, nc = id & 31;   // 16 k-rows x 32 chunks
                CP16(base + A_TILE_BYTES + r * (BNR * 4) + nc * 16,
                     Bp + (size_t)(k0 + r) * ldb + bn + nc * 4);
            }
        }
        CP_COMMIT();
    };

    float c[4][4][4] = {};

    issue(0);
    issue(1);

    for (int it = 0; it < kch; ++it) {
        CP_WAIT1();
        __syncthreads();
        if (it + 2 < kch) issue(it + 2);
        else CP_COMMIT();
        const float* As = (const float*)(smraw + (it % STAGES) * STAGE_BYTES);
        const float* Bs = As + A_TILE_BYTES / 4;
        mma_stage<(EPI == 2) ? 1 : 0>(As, Bs, wm, wn, lr, lc, c);
    }

    // ---- epilogue ----
    const float scale = rsqrtf((float)A_);
#pragma unroll
    for (int i = 0; i < 4; i++)
#pragma unroll
        for (int j = 0; j < 4; j++) {
            const int r0 = qm + wm + 16 * i + lr;
            const int cc = bn + wn + 8 * j + 2 * lc;
            if (EPI == 0) {
                *(float2*)&Cp[(size_t)r0 * A_ + cc] =
                    make_float2(rnd_tf(c[i][j][0]), rnd_tf(c[i][j][1]));
                *(float2*)&Cp[(size_t)(r0 + 8) * A_ + cc] =
                    make_float2(rnd_tf(c[i][j][2]), rnd_tf(c[i][j][3]));
            } else if (EPI == 1) {
                float2 w0, w1;
                w0.x = (cc     <= r0) ? c[i][j][0] * scale : NEG_INF;
                w0.y = (cc + 1 <= r0) ? c[i][j][1] * scale : NEG_INF;
                w1.x = (cc     <= r0 + 8) ? c[i][j][2] * scale : NEG_INF;
                w1.y = (cc + 1 <= r0 + 8) ? c[i][j][3] * scale : NEG_INF;
                *(float2*)&Cp[(size_t)r0 * S_ + cc] = w0;
                *(float2*)&Cp[(size_t)(r0 + 8) * S_ + cc] = w1;
            } else {
                *(float2*)&Cp[(size_t)r0 * A_ + cc] =
                    make_float2(rintf(c[i][j][0] * 1e4f) * 1e-4f,
                                rintf(c[i][j][1] * 1e4f) * 1e-4f);
                *(float2*)&Cp[(size_t)(r0 + 8) * A_ + cc] =
                    make_float2(rintf(c[i][j][2] * 1e4f) * 1e-4f,
                                rintf(c[i][j][3] * 1e4f) * 1e-4f);
            }
        }
}

// ---------------------------------------------------------------------------
// elementwise rna-round to tf32 grid (prepass) — makes mma's tf32 truncation
// a no-op, so inner loops need no cvt and numerics match round 2 exactly.
// ---------------------------------------------------------------------------
__global__ void round_k(const float* __restrict__ in, float* __restrict__ out, int n4) {
    const int i = blockIdx.x * 256 + threadIdx.x;
    if (i < n4) {
        float4 v = ((const float4*)in)[i];
        v.x = rnd_tf(v.x); v.y = rnd_tf(v.y); v.z = rnd_tf(v.z); v.w = rnd_tf(v.w);
        ((float4*)out)[i] = v;
    }
}

// ---------------------------------------------------------------------------
// row softmax over the causal prefix only; writes tf32-rounded probs.
// klen = roundup(q+1, 128); PV never reads beyond it.
// ---------------------------------------------------------------------------
__global__ void __launch_bounds__(256)
softmax_kernel() {
    const size_t row = blockIdx.x;
    const int q = (int)(row & (S_ - 1));
    const int klen = (q & ~127) + 128;
    float* __restrict__ p = g_P + row * S_;
    const int tid = threadIdx.x;
    __shared__ float red[8];

    float m = NEG_INF;
    for (int i = tid; i < klen; i += 256) m = fmaxf(m, p[i]);
#pragma unroll
    for (int o = 16; o > 0; o >>= 1) m = fmaxf(m, __shfl_xor_sync(0xffffffff, m, o));
    if ((tid & 31) == 0) red[tid >> 5] = m;
    __syncthreads();
    if (tid < 32) {
        float v = (tid < 8) ? red[tid] : NEG_INF;
#pragma unroll
        for (int o = 4; o > 0; o >>= 1) v = fmaxf(v, __shfl_xor_sync(0xffffffff, v, o));
        if (tid == 0) red[0] = v;
    }
    __syncthreads();
    const float M = red[0];
    __syncthreads();

    float s = 0.f;
    for (int i = tid; i < klen; i += 256) {
        float e = __expf(p[i] - M);
        p[i] = e;
        s += e;
    }
#pragma unroll
    for (int o = 16; o > 0; o >>= 1) s += __shfl_xor_sync(0xffffffff, s, o);
    if ((tid & 31) == 0) red[tid >> 5] = s;
    __syncthreads();
    if (tid < 32) {
        float v = (tid < 8) ? red[tid] : 0.f;
#pragma unroll
        for (int o = 4; o > 0; o >>= 1) v += __shfl_xor_sync(0xffffffff, v, o);
        if (tid == 0) red[0] = v;
    }
    __syncthreads();
    const float inv = 1.f / red[0];

    for (int i = tid; i < klen; i += 256) p[i] = rnd_tf(p[i] * inv);
}

// ---------------------------------------------------------------------------
extern "C" void kernel_launch(void* const* d_in, const int* in_sizes, int n_in,
                              void* d_out, int out_size) {
    const float* x  = (const float*)d_in[0];   // embedded [B,S,E]
    const float* Wk = (const float*)d_in[1];
    const float* Wq = (const float*)d_in[2];
    const float* Wv = (const float*)d_in[3];
    float* out = (float*)d_out;

    float *dX, *dWq, *dWk, *dWv, *dQ, *dK, *dV, *dP;
    cudaGetSymbolAddress((void**)&dX,  g_X);
    cudaGetSymbolAddress((void**)&dWq, g_Wq);
    cudaGetSymbolAddress((void**)&dWk, g_Wk);
    cudaGetSymbolAddress((void**)&dWv, g_Wv);
    cudaGetSymbolAddress((void**)&dQ,  g_Q);
    cudaGetSymbolAddress((void**)&dK,  g_K);
    cudaGetSymbolAddress((void**)&dV,  g_V);
    cudaGetSymbolAddress((void**)&dP,  g_P);

    cudaFuncSetAttribute(gemm_tc<0>, cudaFuncAttributeMaxDynamicSharedMemorySize, SMEM_DYN);
    cudaFuncSetAttribute(gemm_tc<1>, cudaFuncAttributeMaxDynamicSharedMemorySize, SMEM_DYN);
    cudaFuncSetAttribute(gemm_tc<2>, cudaFuncAttributeMaxDynamicSharedMemorySize, SMEM_DYN);

    // prepass: rna-round inputs to tf32 grid
    const int XN4 = B_ * S_ * E_ / 4;
    const int WN4 = A_ * E_ / 4;
    round_k<<<(XN4 + 255) / 256, 256>>>(x,  dX,  XN4);
    round_k<<<(WN4 + 255) / 256, 256>>>(Wq, dWq, WN4);
    round_k<<<(WN4 + 255) / 256, 256>>>(Wk, dWk, WN4);
    round_k<<<(WN4 + 255) / 256, 256>>>(Wv, dWv, WN4);

    // projections: M = B*S = 16384, N = A = 2048, K = E = 2048
    dim3 gproj(A_ / TN, (B_ * S_) / TM, 1);
    gemm_tc<0><<<gproj, NTH, SMEM_DYN>>>(dX, dWq, dQ);
    gemm_tc<0><<<gproj, NTH, SMEM_DYN>>>(dX, dWk, dK);
    gemm_tc<0><<<gproj, NTH, SMEM_DYN>>>(dX, dWv, dV);

    // scores (causal) per batch: S x S
    dim3 gsc(S_ / TN, S_ / TM, B_);
    gemm_tc<1><<<gsc, NTH, SMEM_DYN>>>(dQ, dK, dP);

    softmax_kernel<<<B_ * S_, 256>>>();

    // P @ V (causal K-limit), output rounded to 4 decimals
    dim3 gpv(A_ / TN, S_ / TM, B_);
    gemm_tc<2><<<gpv, NTH, SMEM_DYN>>>(dP, dV, out);
}

// round 6
// speedup vs baseline: 3.6303x; 1.0298x over previous
#include <cuda_runtime.h>
#include <math.h>
#include <stdint.h>

// Problem constants
#define B_ 4
#define S_ 4096
#define E_ 2048
#define A_ 2048

// Legacy mma.sync tf32 path (tcgen05 unavailable: harness PTX target is sm_103)
// CTA tile 128x128, 4 warps, warp tile 64x64 (16 FLOP per LDS byte)
#define TM 128
#define TN 128
#define BK 16
#define STAGES 4
#define NTH 128

#define ASR 20          // A smem row stride (floats): 16 data + 4 pad, rows 16B-aligned
#define BSR 20          // B K-major smem row stride
#define BNR 136         // B N-major smem row stride (PV): 544B, 16B-aligned
#define A_TILE_BYTES (TM * ASR * 4)            // 10240
#define B_TILE_BYTES (TM * BSR * 4)            // 10240 (>= 16*BNR*4 = 8704)
#define STAGE_BYTES (A_TILE_BYTES + B_TILE_BYTES)
#define SMEM_DYN (STAGES * STAGE_BYTES)        // 81920

#define NEG_INF (-1e30f)

// Scratch (allocation-free rule: __device__ globals)
__device__ float g_X [(size_t)B_ * S_ * E_];
__device__ float g_Wq[(size_t)A_ * E_];
__device__ float g_Wk[(size_t)A_ * E_];
__device__ float g_Wv[(size_t)A_ * E_];
__device__ float g_Q [(size_t)B_ * S_ * A_];
__device__ float g_K [(size_t)B_ * S_ * A_];
__device__ float g_V [(size_t)B_ * S_ * A_];
__device__ float g_P [(size_t)B_ * S_ * S_];

// ---------------------------------------------------------------------------
// helpers
// ---------------------------------------------------------------------------
__device__ __forceinline__ uint32_t f2tf(float x) {
    uint32_t r; asm("cvt.rna.tf32.f32 %0, %1;" : "=r"(r) : "f"(x)); return r;
}
__device__ __forceinline__ float rnd_tf(float x) { return __uint_as_float(f2tf(x)); }
__device__ __forceinline__ uint32_t s2u(const void* p) {
    uint32_t a;
    asm("{ .reg .u64 t; cvta.to.shared.u64 t, %1; cvt.u32.u64 %0, t; }" : "=r"(a) : "l"(p));
    return a;
}

#define CP16(sm, g) \
    asm volatile("cp.async.cg.shared.global [%0], [%1], 16;" :: "r"(sm), "l"(g) : "memory")
#define CP_COMMIT() asm volatile("cp.async.commit_group;" ::: "memory")
#define CP_WAIT2()  asm volatile("cp.async.wait_group 2;" ::: "memory")

#define MMA_TF32(C, Af, Bf)                                                   \
    asm volatile(                                                             \
        "mma.sync.aligned.m16n8k8.row.col.f32.tf32.tf32.f32 "                 \
        "{%0,%1,%2,%3}, {%4,%5,%6,%7}, {%8,%9}, {%0,%1,%2,%3};"               \
        : "+f"((C)[0]), "+f"((C)[1]), "+f"((C)[2]), "+f"((C)[3])              \
        : "r"((Af)[0]), "r"((Af)[1]), "r"((Af)[2]), "r"((Af)[3]),             \
          "r"((Bf)[0]), "r"((Bf)[1]))

// ---------------------------------------------------------------------------
// one BK=16 slab of mma work, 64x64 warp tile.
// BLAY: 0 = B K-major [n][k], 1 = B N-major [k][n]
// ---------------------------------------------------------------------------
template <int BLAY>
__device__ __forceinline__ void mma_stage(const float* __restrict__ As,
                                          const float* __restrict__ Bs,
                                          int wm, int wn, int lr, int lc,
                                          float c[4][8][4]) {
#pragma unroll
    for (int kk = 0; kk < BK; kk += 8) {
        uint32_t a[4][4], b[8][2];
#pragma unroll
        for (int i = 0; i < 4; i++) {
            const float* p = As + (wm + 16 * i + lr) * ASR + kk + lc;
            a[i][0] = __float_as_uint(p[0]);
            a[i][1] = __float_as_uint(p[8 * ASR]);
            a[i][2] = __float_as_uint(p[4]);
            a[i][3] = __float_as_uint(p[8 * ASR + 4]);
        }
#pragma unroll
        for (int j = 0; j < 8; j++) {
            if (BLAY == 0) {
                const float* p = Bs + (wn + 8 * j + lr) * BSR + kk + lc;
                b[j][0] = __float_as_uint(p[0]);
                b[j][1] = __float_as_uint(p[4]);
            } else {
                const float* p = Bs + (kk + lc) * BNR + wn + 8 * j + lr;
                b[j][0] = __float_as_uint(p[0]);
                b[j][1] = __float_as_uint(p[4 * BNR]);
            }
        }
#pragma unroll
        for (int i = 0; i < 4; i++)
#pragma unroll
            for (int j = 0; j < 8; j++) MMA_TF32(c[i][j], a[i], b[j]);
    }
}

// ---------------------------------------------------------------------------
// unified GEMM. EPI: 0 = projection (round-to-tf32 output),
//                1 = scores (scale + causal mask), 2 = PV (round to 4 dp)
// A always [M][K] row-major (K-major); B: EPI<2 -> [N][K], EPI==2 -> [K][N]
// ---------------------------------------------------------------------------
template <int EPI>
__global__ void __launch_bounds__(NTH, 2)
gemm_tc(const float* __restrict__ Ab, const float* __restrict__ Bb,
        float* __restrict__ Cb) {
    const int bz = blockIdx.z;
    const int qm = blockIdx.y * TM;
    const int bn = blockIdx.x * TN;

    if (EPI == 1 && bn >= qm + TM) return;   // fully masked score tile: skip

    const float* Ap; const float* Bp; float* Cp;
    int lda, ldb, kch;
    if (EPI == 0) {
        Ap = Ab; Bp = Bb; Cp = Cb;
        lda = E_; ldb = E_; kch = E_ / BK;
    } else if (EPI == 1) {
        Ap = Ab + (size_t)bz * S_ * A_;
        Bp = Bb + (size_t)bz * S_ * A_;
        Cp = Cb + (size_t)bz * S_ * S_;
        lda = A_; ldb = A_; kch = A_ / BK;
    } else {
        Ap = Ab + (size_t)bz * S_ * S_;
        Bp = Bb + (size_t)bz * S_ * A_;
        Cp = Cb + (size_t)bz * S_ * A_;
        lda = S_; ldb = A_; kch = (qm + TM) / BK;   // causal K truncation
    }

    extern __shared__ char smraw[];
    const uint32_t sb = s2u(smraw);
    const int tid = threadIdx.x, lane = tid & 31, warp = tid >> 5;
    const int lr = lane >> 2, lc = lane & 3;
    const int wm = (warp >> 1) * 64, wn = (warp & 1) * 64;

    const float* Arow = Ap + (size_t)qm * lda;

    // ---- async loaders: 8 x 16B per thread per stage ----
    auto issue = [&](int it) {
        const uint32_t base = sb + (it & (STAGES - 1)) * STAGE_BYTES;
        const int k0 = it * BK;
        // A: 512 chunks (128 rows x 4), 4 per thread
#pragma unroll
        for (int h = 0; h < 4; h++) {
            const int id = tid + h * NTH;
            const int r = id >> 2, cch = id & 3;
            CP16(base + r * (ASR * 4) + cch * 16,
                 Arow + (size_t)r * lda + k0 + cch * 4);
        }
        // B: 512 chunks
        if (EPI < 2) {
#pragma unroll
            for (int h = 0; h < 4; h++) {
                const int id = tid + h * NTH;
                const int r = id >> 2, cch = id & 3;
                CP16(base + A_TILE_BYTES + r * (BSR * 4) + cch * 16,
                     Bp + (size_t)(bn + r) * ldb + k0 + cch * 4);
            }
        } else {
#pragma unroll
            for (int h = 0; h < 4; h++) {
                const int id = tid + h * NTH;
                const int r = id >> 5, nc = id & 31;   // 16 k-rows x 32 chunks
                CP16(base + A_TILE_BYTES + r * (BNR * 4) + nc * 16,
                     Bp + (size_t)(k0 + r) * ldb + bn + nc * 4);
            }
        }
        CP_COMMIT();
    };

    float c[4][8][4] = {};

    issue(0);
    issue(1);
    issue(2);

    for (int it = 0; it < kch; ++it) {
        CP_WAIT2();
        __syncthreads();
        if (it + 3 < kch) issue(it + 3);
        else CP_COMMIT();
        const float* As = (const float*)(smraw + (it & (STAGES - 1)) * STAGE_BYTES);
        const float* Bs = As + A_TILE_BYTES / 4;
        mma_stage<(EPI == 2) ? 1 : 0>(As, Bs, wm, wn, lr, lc, c);
    }

    // ---- epilogue ----
    const float scale = rsqrtf((float)A_);
#pragma unroll
    for (int i = 0; i < 4; i++)
#pragma unroll
        for (int j = 0; j < 8; j++) {
            const int r0 = qm + wm + 16 * i + lr;
            const int cc = bn + wn + 8 * j + 2 * lc;
            if (EPI == 0) {
                *(float2*)&Cp[(size_t)r0 * A_ + cc] =
                    make_float2(rnd_tf(c[i][j][0]), rnd_tf(c[i][j][1]));
                *(float2*)&Cp[(size_t)(r0 + 8) * A_ + cc] =
                    make_float2(rnd_tf(c[i][j][2]), rnd_tf(c[i][j][3]));
            } else if (EPI == 1) {
                float2 w0, w1;
                w0.x = (cc     <= r0) ? c[i][j][0] * scale : NEG_INF;
                w0.y = (cc + 1 <= r0) ? c[i][j][1] * scale : NEG_INF;
                w1.x = (cc     <= r0 + 8) ? c[i][j][2] * scale : NEG_INF;
                w1.y = (cc + 1 <= r0 + 8) ? c[i][j][3] * scale : NEG_INF;
                *(float2*)&Cp[(size_t)r0 * S_ + cc] = w0;
                *(float2*)&Cp[(size_t)(r0 + 8) * S_ + cc] = w1;
            } else {
                *(float2*)&Cp[(size_t)r0 * A_ + cc] =
                    make_float2(rintf(c[i][j][0] * 1e4f) * 1e-4f,
                                rintf(c[i][j][1] * 1e4f) * 1e-4f);
                *(float2*)&Cp[(size_t)(r0 + 8) * A_ + cc] =
                    make_float2(rintf(c[i][j][2] * 1e4f) * 1e-4f,
                                rintf(c[i][j][3] * 1e4f) * 1e-4f);
            }
        }
}

// ---------------------------------------------------------------------------
// elementwise rna-round to tf32 grid (prepass) — makes mma's tf32 truncation
// a no-op, so inner loops need no cvt; numerics match rounds 2/5 exactly.
// ---------------------------------------------------------------------------
__global__ void round_k(const float* __restrict__ in, float* __restrict__ out, int n4) {
    const int i = blockIdx.x * 256 + threadIdx.x;
    if (i < n4) {
        float4 v = ((const float4*)in)[i];
        v.x = rnd_tf(v.x); v.y = rnd_tf(v.y); v.z = rnd_tf(v.z); v.w = rnd_tf(v.w);
        ((float4*)out)[i] = v;
    }
}

// ---------------------------------------------------------------------------
// row softmax over the causal prefix only; writes tf32-rounded probs.
// klen = roundup(q+1, 128); PV never reads beyond it.
// ---------------------------------------------------------------------------
__global__ void __launch_bounds__(256)
softmax_kernel() {
    const size_t row = blockIdx.x;
    const int q = (int)(row & (S_ - 1));
    const int klen = (q & ~127) + 128;
    float* __restrict__ p = g_P + row * S_;
    const int tid = threadIdx.x;
    __shared__ float red[8];

    float m = NEG_INF;
    for (int i = tid; i < klen; i += 256) m = fmaxf(m, p[i]);
#pragma unroll
    for (int o = 16; o > 0; o >>= 1) m = fmaxf(m, __shfl_xor_sync(0xffffffff, m, o));
    if ((tid & 31) == 0) red[tid >> 5] = m;
    __syncthreads();
    if (tid < 32) {
        float v = (tid < 8) ? red[tid] : NEG_INF;
#pragma unroll
        for (int o = 4; o > 0; o >>= 1) v = fmaxf(v, __shfl_xor_sync(0xffffffff, v, o));
        if (tid == 0) red[0] = v;
    }
    __syncthreads();
    const float M = red[0];
    __syncthreads();

    float s = 0.f;
    for (int i = tid; i < klen; i += 256) {
        float e = __expf(p[i] - M);
        p[i] = e;
        s += e;
    }
#pragma unroll
    for (int o = 16; o > 0; o >>= 1) s += __shfl_xor_sync(0xffffffff, s, o);
    if ((tid & 31) == 0) red[tid >> 5] = s;
    __syncthreads();
    if (tid < 32) {
        float v = (tid < 8) ? red[tid] : 0.f;
#pragma unroll
        for (int o = 4; o > 0; o >>= 1) v += __shfl_xor_sync(0xffffffff, v, o);
        if (tid == 0) red[0] = v;
    }
    __syncthreads();
    const float inv = 1.f / red[0];

    for (int i = tid; i < klen; i += 256) p[i] = rnd_tf(p[i] * inv);
}

// ---------------------------------------------------------------------------
extern "C" void kernel_launch(void* const* d_in, const int* in_sizes, int n_in,
                              void* d_out, int out_size) {
    const float* x  = (const float*)d_in[0];   // embedded [B,S,E]
    const float* Wk = (const float*)d_in[1];
    const float* Wq = (const float*)d_in[2];
    const float* Wv = (const float*)d_in[3];
    float* out = (float*)d_out;

    float *dX, *dWq, *dWk, *dWv, *dQ, *dK, *dV, *dP;
    cudaGetSymbolAddress((void**)&dX,  g_X);
    cudaGetSymbolAddress((void**)&dWq, g_Wq);
    cudaGetSymbolAddress((void**)&dWk, g_Wk);
    cudaGetSymbolAddress((void**)&dWv, g_Wv);
    cudaGetSymbolAddress((void**)&dQ,  g_Q);
    cudaGetSymbolAddress((void**)&dK,  g_K);
    cudaGetSymbolAddress((void**)&dV,  g_V);
    cudaGetSymbolAddress((void**)&dP,  g_P);

    cudaFuncSetAttribute(gemm_tc<0>, cudaFuncAttributeMaxDynamicSharedMemorySize, SMEM_DYN);
    cudaFuncSetAttribute(gemm_tc<1>, cudaFuncAttributeMaxDynamicSharedMemorySize, SMEM_DYN);
    cudaFuncSetAttribute(gemm_tc<2>, cudaFuncAttributeMaxDynamicSharedMemorySize, SMEM_DYN);

    // prepass: rna-round inputs to tf32 grid
    const int XN4 = B_ * S_ * E_ / 4;
    const int WN4 = A_ * E_ / 4;
    round_k<<<(XN4 + 255) / 256, 256>>>(x,  dX,  XN4);
    round_k<<<(WN4 + 255) / 256, 256>>>(Wq, dWq, WN4);
    round_k<<<(WN4 + 255) / 256, 256>>>(Wk, dWk, WN4);
    round_k<<<(WN4 + 255) / 256, 256>>>(Wv, dWv, WN4);

    // projections: M = B*S = 16384, N = A = 2048, K = E = 2048
    dim3 gproj(A_ / TN, (B_ * S_) / TM, 1);
    gemm_tc<0><<<gproj, NTH, SMEM_DYN>>>(dX, dWq, dQ);
    gemm_tc<0><<<gproj, NTH, SMEM_DYN>>>(dX, dWk, dK);
    gemm_tc<0><<<gproj, NTH, SMEM_DYN>>>(dX, dWv, dV);

    // scores (causal) per batch: S x S
    dim3 gsc(S_ / TN, S_ / TM, B_);
    gemm_tc<1><<<gsc, NTH, SMEM_DYN>>>(dQ, dK, dP);

    softmax_kernel<<<B_ * S_, 256>>>();

    // P @ V (causal K-limit), output rounded to 4 decimals
    dim3 gpv(A_ / TN, S_ / TM, B_);
    gemm_tc<2><<<gpv, NTH, SMEM_DYN>>>(dP, dV, out);
}

// round 7
// speedup vs baseline: 6.8190x; 1.8784x over previous
#include <cuda_runtime.h>
#include <cuda_fp16.h>
#include <math.h>
#include <stdint.h>

// Problem constants
#define B_ 4
#define S_ 4096
#define E_ 2048
#define A_ 2048

// Legacy mma.sync fp16 path (tcgen05 unavailable: harness PTX target is sm_103).
// fp16 has the same 11-bit significand as tf32 -> same quantization error,
// 2x the mma throughput, half the memory traffic.
#define TM 128
#define TN 128
#define BK 32            // halfs per stage-slab (64B rows)
#define STAGES 4
#define NTH 128

#define ASR 40           // smem row stride in halfs (80B): rows 16B-aligned and the
                         // 8-row fragment pattern covers all 32 banks exactly once
#define A_TILE_BYTES (TM * ASR * 2)            // 10240
#define B_TILE_BYTES (TN * ASR * 2)            // 10240
#define STAGE_BYTES (A_TILE_BYTES + B_TILE_BYTES)
#define SMEM_DYN (STAGES * STAGE_BYTES)        // 81920

#define NEG_INF (-1e30f)

// Scratch (allocation-free rule: __device__ globals)
__device__ __half g_Xh [(size_t)B_ * S_ * E_];
__device__ __half g_Wqh[(size_t)A_ * E_];
__device__ __half g_Wkh[(size_t)A_ * E_];
__device__ __half g_Wvh[(size_t)A_ * E_];
__device__ __half g_Qh [(size_t)B_ * S_ * A_];
__device__ __half g_Kh [(size_t)B_ * S_ * A_];
__device__ __half g_Vt [(size_t)B_ * A_ * S_];  // V transposed per batch: [A][S]
__device__ float  g_P  [(size_t)B_ * S_ * S_];  // fp32 scores
__device__ __half g_Ph [(size_t)B_ * S_ * S_];  // fp16 probs

// ---------------------------------------------------------------------------
// helpers
// ---------------------------------------------------------------------------
__device__ __forceinline__ uint32_t s2u(const void* p) {
    uint32_t a;
    asm("{ .reg .u64 t; cvta.to.shared.u64 t, %1; cvt.u32.u64 %0, t; }" : "=r"(a) : "l"(p));
    return a;
}

#define CP16(sm, g) \
    asm volatile("cp.async.cg.shared.global [%0], [%1], 16;" :: "r"(sm), "l"(g) : "memory")
#define CP_COMMIT() asm volatile("cp.async.commit_group;" ::: "memory")
#define CP_WAIT2()  asm volatile("cp.async.wait_group 2;" ::: "memory")
#define CP_WAIT0()  asm volatile("cp.async.wait_group 0;" ::: "memory")

#define MMA_F16(C, Aa, Bb)                                                    \
    asm volatile(                                                             \
        "mma.sync.aligned.m16n8k16.row.col.f32.f16.f16.f32 "                  \
        "{%0,%1,%2,%3}, {%4,%5,%6,%7}, {%8,%9}, {%0,%1,%2,%3};"               \
        : "+f"((C)[0]), "+f"((C)[1]), "+f"((C)[2]), "+f"((C)[3])              \
        : "r"((Aa)[0]), "r"((Aa)[1]), "r"((Aa)[2]), "r"((Aa)[3]),             \
          "r"((Bb)[0]), "r"((Bb)[1]))

// ---------------------------------------------------------------------------
// one BK=32 slab: 2 x k16 substeps, 64x64 warp tile
// ---------------------------------------------------------------------------
__device__ __forceinline__ void mma_stage(const __half* __restrict__ As,
                                          const __half* __restrict__ Bs,
                                          int wm, int wn, int lr, int lc,
                                          float c[4][8][4]) {
#pragma unroll
    for (int kk = 0; kk < BK; kk += 16) {
        uint32_t a[4][4], b[8][2];
#pragma unroll
        for (int i = 0; i < 4; i++) {
            const __half* p = As + (wm + 16 * i + lr) * ASR + kk + 2 * lc;
            a[i][0] = *(const uint32_t*)(p);
            a[i][1] = *(const uint32_t*)(p + 8 * ASR);
            a[i][2] = *(const uint32_t*)(p + 8);
            a[i][3] = *(const uint32_t*)(p + 8 * ASR + 8);
        }
#pragma unroll
        for (int j = 0; j < 8; j++) {
            const __half* p = Bs + (wn + 8 * j + lr) * ASR + kk + 2 * lc;
            b[j][0] = *(const uint32_t*)(p);
            b[j][1] = *(const uint32_t*)(p + 8);
        }
#pragma unroll
        for (int i = 0; i < 4; i++)
#pragma unroll
            for (int j = 0; j < 8; j++) MMA_F16(c[i][j], a[i], b[j]);
    }
}

// ---------------------------------------------------------------------------
// unified fp16 GEMM, all B operands K-major [n][k].
// EPI: 0 = proj -> half row-major (Q/K)
//      1 = proj -> half transposed (Vt[a][s])
//      2 = scores -> fp32 + scale + causal mask
//      3 = PV -> fp32 rounded to 4 decimals
// ---------------------------------------------------------------------------
template <int EPI>
__global__ void __launch_bounds__(NTH, 2)
gemm_h(const void* __restrict__ Abv, const void* __restrict__ Bbv,
       void* __restrict__ Cbv) {
    const int bz = blockIdx.z;
    const int qm = blockIdx.y * TM;
    const int bn = blockIdx.x * TN;

    if (EPI == 2 && bn >= qm + TM) return;   // fully masked score tile

    const __half* Ap; const __half* Bp;
    int lda, ldb, kch;
    if (EPI <= 1) {
        Ap = (const __half*)Abv; Bp = (const __half*)Bbv;
        lda = E_; ldb = E_; kch = E_ / BK;
    } else if (EPI == 2) {
        Ap = (const __half*)Abv + (size_t)bz * S_ * A_;
        Bp = (const __half*)Bbv + (size_t)bz * S_ * A_;
        lda = A_; ldb = A_; kch = A_ / BK;
    } else {
        Ap = (const __half*)Abv + (size_t)bz * S_ * S_;
        Bp = (const __half*)Bbv + (size_t)bz * A_ * S_;
        lda = S_; ldb = S_; kch = (qm + TM) / BK;   // causal K truncation
    }

    extern __shared__ char smraw[];
    const uint32_t sb = s2u(smraw);
    const int tid = threadIdx.x, lane = tid & 31, warp = tid >> 5;
    const int lr = lane >> 2, lc = lane & 3;
    const int wm = (warp >> 1) * 64, wn = (warp & 1) * 64;

    const __half* Arow = Ap + (size_t)qm * lda;

    // ---- async loaders: 8 x 16B per thread per stage ----
    auto issue = [&](int it) {
        const uint32_t base = sb + (it & (STAGES - 1)) * STAGE_BYTES;
        const int k0 = it * BK;
#pragma unroll
        for (int h = 0; h < 4; h++) {          // A: 512 chunks (128 rows x 4)
            const int id = tid + h * NTH;
            const int r = id >> 2, cch = id & 3;
            CP16(base + r * 80 + cch * 16,
                 Arow + (size_t)r * lda + k0 + cch * 8);
        }
#pragma unroll
        for (int h = 0; h < 4; h++) {          // B: 512 chunks
            const int id = tid + h * NTH;
            const int r = id >> 2, cch = id & 3;
            CP16(base + A_TILE_BYTES + r * 80 + cch * 16,
                 Bp + (size_t)(bn + r) * ldb + k0 + cch * 8);
        }
        CP_COMMIT();
    };

    float c[4][8][4] = {};

    issue(0);
    issue(1);
    issue(2);

    for (int it = 0; it < kch; ++it) {
        CP_WAIT2();
        __syncthreads();
        if (it + 3 < kch) issue(it + 3);
        else CP_COMMIT();
        const __half* As = (const __half*)(smraw + (it & (STAGES - 1)) * STAGE_BYTES);
        const __half* Bs = As + A_TILE_BYTES / 2;
        mma_stage(As, Bs, wm, wn, lr, lc, c);
    }

    // ---- epilogues ----
    if (EPI == 0) {
        __half* Cp = (__half*)Cbv;
#pragma unroll
        for (int i = 0; i < 4; i++)
#pragma unroll
            for (int j = 0; j < 8; j++) {
                const int r0 = qm + wm + 16 * i + lr;
                const int cc = bn + wn + 8 * j + 2 * lc;
                *(__half2*)&Cp[(size_t)r0 * A_ + cc] =
                    __floats2half2_rn(c[i][j][0], c[i][j][1]);
                *(__half2*)&Cp[(size_t)(r0 + 8) * A_ + cc] =
                    __floats2half2_rn(c[i][j][2], c[i][j][3]);
            }
    } else if (EPI == 1) {
        // transpose through smem, then coalesced writes to Vt[a][s]
        CP_WAIT0();
        __syncthreads();
        __half* smT = (__half*)smraw;          // [n][m], stride 136 halfs
#pragma unroll
        for (int i = 0; i < 4; i++)
#pragma unroll
            for (int j = 0; j < 8; j++) {
                const int m = wm + 16 * i + lr;
                const int n = wn + 8 * j + 2 * lc;
                smT[(n    ) * 136 + m]     = __float2half_rn(c[i][j][0]);
                smT[(n + 1) * 136 + m]     = __float2half_rn(c[i][j][1]);
                smT[(n    ) * 136 + m + 8] = __float2half_rn(c[i][j][2]);
                smT[(n + 1) * 136 + m + 8] = __float2half_rn(c[i][j][3]);
            }
        __syncthreads();
        const int b = qm >> 12, s0 = qm & (S_ - 1);
        __half* Vt = (__half*)Cbv + (size_t)b * A_ * S_ + s0;
        for (int nn = 0; nn < 32; nn++) {
            const int n = warp * 32 + nn;
            uint2 v = *(const uint2*)(smT + n * 136 + lane * 4);
            *(uint2*)(Vt + (size_t)(bn + n) * S_ + lane * 4) = v;
        }
    } else if (EPI == 2) {
        float* Cp = (float*)Cbv + (size_t)bz * S_ * S_;
        const float scale = rsqrtf((float)A_);
#pragma unroll
        for (int i = 0; i < 4; i++)
#pragma unroll
            for (int j = 0; j < 8; j++) {
                const int r0 = qm + wm + 16 * i + lr;
                const int cc = bn + wn + 8 * j + 2 * lc;
                float2 w0, w1;
                w0.x = (cc     <= r0) ? c[i][j][0] * scale : NEG_INF;
                w0.y = (cc + 1 <= r0) ? c[i][j][1] * scale : NEG_INF;
                w1.x = (cc     <= r0 + 8) ? c[i][j][2] * scale : NEG_INF;
                w1.y = (cc + 1 <= r0 + 8) ? c[i][j][3] * scale : NEG_INF;
                *(float2*)&Cp[(size_t)r0 * S_ + cc] = w0;
                *(float2*)&Cp[(size_t)(r0 + 8) * S_ + cc] = w1;
            }
    } else {
        float* Cp = (float*)Cbv + (size_t)bz * S_ * A_;
#pragma unroll
        for (int i = 0; i < 4; i++)
#pragma unroll
            for (int j = 0; j < 8; j++) {
                const int r0 = qm + wm + 16 * i + lr;
                const int cc = bn + wn + 8 * j + 2 * lc;
                *(float2*)&Cp[(size_t)r0 * A_ + cc] =
                    make_float2(rintf(c[i][j][0] * 1e4f) * 1e-4f,
                                rintf(c[i][j][1] * 1e4f) * 1e-4f);
                *(float2*)&Cp[(size_t)(r0 + 8) * A_ + cc] =
                    make_float2(rintf(c[i][j][2] * 1e4f) * 1e-4f,
                                rintf(c[i][j][3] * 1e4f) * 1e-4f);
            }
    }
}

// ---------------------------------------------------------------------------
// prepass: fp32 -> fp16 (rn) conversion, 8 elems/thread
// ---------------------------------------------------------------------------
__global__ void round_h(const float* __restrict__ in, __half* __restrict__ out,
                        int n8) {
    const int i = blockIdx.x * 256 + threadIdx.x;
    if (i < n8) {
        const float4* i4 = (const float4*)in + (size_t)i * 2;
        float4 v0 = i4[0], v1 = i4[1];
        __half2* o2 = (__half2*)(out + (size_t)i * 8);
        o2[0] = __floats2half2_rn(v0.x, v0.y);
        o2[1] = __floats2half2_rn(v0.z, v0.w);
        o2[2] = __floats2half2_rn(v1.x, v1.y);
        o2[3] = __floats2half2_rn(v1.z, v1.w);
    }
}

// ---------------------------------------------------------------------------
// row softmax over the causal prefix (fp32 scores in g_P), probs -> fp16 g_Ph
// ---------------------------------------------------------------------------
__global__ void __launch_bounds__(256)
softmax_kernel() {
    const size_t row = blockIdx.x;
    const int q = (int)(row & (S_ - 1));
    const int klen = (q & ~127) + 128;
    float* __restrict__ p = g_P + row * S_;
    __half* __restrict__ ph = g_Ph + row * S_;
    const int tid = threadIdx.x;
    __shared__ float red[8];

    float m = NEG_INF;
    for (int i = tid; i < klen; i += 256) m = fmaxf(m, p[i]);
#pragma unroll
    for (int o = 16; o > 0; o >>= 1) m = fmaxf(m, __shfl_xor_sync(0xffffffff, m, o));
    if ((tid & 31) == 0) red[tid >> 5] = m;
    __syncthreads();
    if (tid < 32) {
        float v = (tid < 8) ? red[tid] : NEG_INF;
#pragma unroll
        for (int o = 4; o > 0; o >>= 1) v = fmaxf(v, __shfl_xor_sync(0xffffffff, v, o));
        if (tid == 0) red[0] = v;
    }
    __syncthreads();
    const float M = red[0];
    __syncthreads();

    float s = 0.f;
    for (int i = tid; i < klen; i += 256) {
        float e = __expf(p[i] - M);
        p[i] = e;
        s += e;
    }
#pragma unroll
    for (int o = 16; o > 0; o >>= 1) s += __shfl_xor_sync(0xffffffff, s, o);
    if ((tid & 31) == 0) red[tid >> 5] = s;
    __syncthreads();
    if (tid < 32) {
        float v = (tid < 8) ? red[tid] : 0.f;
#pragma unroll
        for (int o = 4; o > 0; o >>= 1) v += __shfl_xor_sync(0xffffffff, v, o);
        if (tid == 0) red[0] = v;
    }
    __syncthreads();
    const float inv = 1.f / red[0];

    for (int i = tid; i < klen; i += 256) ph[i] = __float2half_rn(p[i] * inv);
}

// ---------------------------------------------------------------------------
extern "C" void kernel_launch(void* const* d_in, const int* in_sizes, int n_in,
                              void* d_out, int out_size) {
    const float* x  = (const float*)d_in[0];   // embedded [B,S,E]
    const float* Wk = (const float*)d_in[1];
    const float* Wq = (const float*)d_in[2];
    const float* Wv = (const float*)d_in[3];
    float* out = (float*)d_out;

    __half *dXh, *dWqh, *dWkh, *dWvh, *dQh, *dKh, *dVt, *dPh;
    float *dP;
    cudaGetSymbolAddress((void**)&dXh,  g_Xh);
    cudaGetSymbolAddress((void**)&dWqh, g_Wqh);
    cudaGetSymbolAddress((void**)&dWkh, g_Wkh);
    cudaGetSymbolAddress((void**)&dWvh, g_Wvh);
    cudaGetSymbolAddress((void**)&dQh,  g_Qh);
    cudaGetSymbolAddress((void**)&dKh,  g_Kh);
    cudaGetSymbolAddress((void**)&dVt,  g_Vt);
    cudaGetSymbolAddress((void**)&dP,   g_P);
    cudaGetSymbolAddress((void**)&dPh,  g_Ph);

    cudaFuncSetAttribute(gemm_h<0>, cudaFuncAttributeMaxDynamicSharedMemorySize, SMEM_DYN);
    cudaFuncSetAttribute(gemm_h<1>, cudaFuncAttributeMaxDynamicSharedMemorySize, SMEM_DYN);
    cudaFuncSetAttribute(gemm_h<2>, cudaFuncAttributeMaxDynamicSharedMemorySize, SMEM_DYN);
    cudaFuncSetAttribute(gemm_h<3>, cudaFuncAttributeMaxDynamicSharedMemorySize, SMEM_DYN);

    // prepass: fp32 -> fp16 (11-bit significand, same quantization as tf32)
    const int XN8 = B_ * S_ * E_ / 8;
    const int WN8 = A_ * E_ / 8;
    round_h<<<(XN8 + 255) / 256, 256>>>(x,  dXh,  XN8);
    round_h<<<(WN8 + 255) / 256, 256>>>(Wq, dWqh, WN8);
    round_h<<<(WN8 + 255) / 256, 256>>>(Wk, dWkh, WN8);
    round_h<<<(WN8 + 255) / 256, 256>>>(Wv, dWvh, WN8);

    // projections: M = B*S = 16384, N = A = 2048, K = E = 2048
    dim3 gproj(A_ / TN, (B_ * S_) / TM, 1);
    gemm_h<0><<<gproj, NTH, SMEM_DYN>>>(dXh, dWqh, dQh);
    gemm_h<0><<<gproj, NTH, SMEM_DYN>>>(dXh, dWkh, dKh);
    gemm_h<1><<<gproj, NTH, SMEM_DYN>>>(dXh, dWvh, dVt);

    // scores (causal) per batch: S x S, fp32 out
    dim3 gsc(S_ / TN, S_ / TM, B_);
    gemm_h<2><<<gsc, NTH, SMEM_DYN>>>(dQh, dKh, dP);

    softmax_kernel<<<B_ * S_, 256>>>();

    // P @ V^T (causal K-limit), fp32 out rounded to 4 decimals
    dim3 gpv(A_ / TN, S_ / TM, B_);
    gemm_h<3><<<gpv, NTH, SMEM_DYN>>>(dPh, dVt, out);
}

// round 11
// speedup vs baseline: 6.9892x; 1.0250x over previous
#include <cuda_runtime.h>
#include <cuda_fp16.h>
#include <math.h>
#include <stdint.h>

// Problem constants
#define B_ 4
#define S_ 4096
#define E_ 2048
#define A_ 2048

// Legacy mma.sync fp16 path (tcgen05 unavailable: harness PTX target is sm_103).
// fp16 has the same 11-bit significand as tf32 -> same quantization error,
// 2x the mma throughput, half the memory traffic. Measured: mainloop sits at
// the legacy HMMA pipe ceiling (~1024 FLOP/cyc/SM), so this round attacks
// scheduling waste (PV load imbalance, scores wave packing) only.
#define TM 128
#define TN 128
#define BK 32            // halfs per stage-slab (64B rows)
#define STAGES 4
#define NTH 128

#define ASR 40           // smem row stride in halfs (80B)
#define A_TILE_BYTES (TM * ASR * 2)            // 10240
#define B_TILE_BYTES (TN * ASR * 2)            // 10240
#define STAGE_BYTES (A_TILE_BYTES + B_TILE_BYTES)
#define SMEM_DYN (STAGES * STAGE_BYTES)        // 81920

#define NTILES_TRI 528   // 32*33/2 lower-triangle tiles per batch

#define NEG_INF (-1e30f)

// Scratch (allocation-free rule: __device__ globals)
__device__ __half g_Xh [(size_t)B_ * S_ * E_];
__device__ __half g_Wqh[(size_t)A_ * E_];
__device__ __half g_Wkh[(size_t)A_ * E_];
__device__ __half g_Wvh[(size_t)A_ * E_];
__device__ __half g_Qh [(size_t)B_ * S_ * A_];
__device__ __half g_Kh [(size_t)B_ * S_ * A_];
__device__ __half g_Vt [(size_t)B_ * A_ * S_];  // V transposed per batch: [A][S]
__device__ float  g_P  [(size_t)B_ * S_ * S_];  // fp32 scores
__device__ __half g_Ph [(size_t)B_ * S_ * S_];  // fp16 probs

// ---------------------------------------------------------------------------
// helpers
// ---------------------------------------------------------------------------
__device__ __forceinline__ uint32_t s2u(const void* p) {
    uint32_t a;
    asm("{ .reg .u64 t; cvta.to.shared.u64 t, %1; cvt.u32.u64 %0, t; }" : "=r"(a) : "l"(p));
    return a;
}

#define CP16(sm, g) \
    asm volatile("cp.async.cg.shared.global [%0], [%1], 16;" :: "r"(sm), "l"(g) : "memory")
#define CP_COMMIT() asm volatile("cp.async.commit_group;" ::: "memory")
#define CP_WAIT2()  asm volatile("cp.async.wait_group 2;" ::: "memory")
#define CP_WAIT0()  asm volatile("cp.async.wait_group 0;" ::: "memory")

#define MMA_F16(C, Aa, Bb)                                                    \
    asm volatile(                                                             \
        "mma.sync.aligned.m16n8k16.row.col.f32.f16.f16.f32 "                  \
        "{%0,%1,%2,%3}, {%4,%5,%6,%7}, {%8,%9}, {%0,%1,%2,%3};"               \
        : "+f"((C)[0]), "+f"((C)[1]), "+f"((C)[2]), "+f"((C)[3])              \
        : "r"((Aa)[0]), "r"((Aa)[1]), "r"((Aa)[2]), "r"((Aa)[3]),             \
          "r"((Bb)[0]), "r"((Bb)[1]))

// ---------------------------------------------------------------------------
// one BK=32 slab: 2 x k16 substeps, 64x64 warp tile
// ---------------------------------------------------------------------------
__device__ __forceinline__ void mma_stage(const __half* __restrict__ As,
                                          const __half* __restrict__ Bs,
                                          int wm, int wn, int lr, int lc,
                                          float c[4][8][4]) {
#pragma unroll
    for (int kk = 0; kk < BK; kk += 16) {
        uint32_t a[4][4], b[8][2];
#pragma unroll
        for (int i = 0; i < 4; i++) {
            const __half* p = As + (wm + 16 * i + lr) * ASR + kk + 2 * lc;
            a[i][0] = *(const uint32_t*)(p);
            a[i][1] = *(const uint32_t*)(p + 8 * ASR);
            a[i][2] = *(const uint32_t*)(p + 8);
            a[i][3] = *(const uint32_t*)(p + 8 * ASR + 8);
        }
#pragma unroll
        for (int j = 0; j < 8; j++) {
            const __half* p = Bs + (wn + 8 * j + lr) * ASR + kk + 2 * lc;
            b[j][0] = *(const uint32_t*)(p);
            b[j][1] = *(const uint32_t*)(p + 8);
        }
#pragma unroll
        for (int i = 0; i < 4; i++)
#pragma unroll
            for (int j = 0; j < 8; j++) MMA_F16(c[i][j], a[i], b[j]);
    }
}

// ---------------------------------------------------------------------------
// unified fp16 GEMM, all B operands K-major [n][k].
// EPI: 0 = proj -> half row-major (Q/K)
//      1 = proj -> half transposed (Vt[a][s])
//      2 = scores -> fp32 + scale + causal mask (triangle-packed 1D grid)
//      3 = PV -> fp32 rounded to 4 decimals (deepest q-tiles scheduled first)
// ---------------------------------------------------------------------------
template <int EPI>
__global__ void __launch_bounds__(NTH, 2)
gemm_h(const void* __restrict__ Abv, const void* __restrict__ Bbv,
       void* __restrict__ Cbv) {
    const int bz = blockIdx.z;
    int qm, bn;
    if (EPI == 2) {
        // triangular decode: blockIdx.x in [0, 528) -> (qi, ki), ki <= qi
        const int ti = blockIdx.x;
        int qi = (int)((sqrtf(8.f * (float)ti + 1.f) - 1.f) * 0.5f);
        while ((qi + 1) * (qi + 2) / 2 <= ti) qi++;
        while (qi * (qi + 1) / 2 > ti) qi--;
        const int ki = ti - qi * (qi + 1) / 2;
        qm = qi * TM;
        bn = ki * TM;
    } else if (EPI == 3) {
        qm = (int)(gridDim.y - 1 - blockIdx.y) * TM;   // deepest first
        bn = blockIdx.x * TN;
    } else {
        qm = blockIdx.y * TM;
        bn = blockIdx.x * TN;
    }

    const __half* Ap; const __half* Bp;
    int lda, ldb, kch;
    if (EPI <= 1) {
        Ap = (const __half*)Abv; Bp = (const __half*)Bbv;
        lda = E_; ldb = E_; kch = E_ / BK;
    } else if (EPI == 2) {
        Ap = (const __half*)Abv + (size_t)bz * S_ * A_;
        Bp = (const __half*)Bbv + (size_t)bz * S_ * A_;
        lda = A_; ldb = A_; kch = A_ / BK;
    } else {
        Ap = (const __half*)Abv + (size_t)bz * S_ * S_;
        Bp = (const __half*)Bbv + (size_t)bz * A_ * S_;
        lda = S_; ldb = S_; kch = (qm + TM) / BK;   // causal K truncation
    }

    extern __shared__ char smraw[];
    const uint32_t sb = s2u(smraw);
    const int tid = threadIdx.x, lane = tid & 31, warp = tid >> 5;
    const int lr = lane >> 2, lc = lane & 3;
    const int wm = (warp >> 1) * 64, wn = (warp & 1) * 64;

    const __half* Arow = Ap + (size_t)qm * lda;

    // ---- async loaders: 8 x 16B per thread per stage ----
    auto issue = [&](int it) {
        const uint32_t base = sb + (it & (STAGES - 1)) * STAGE_BYTES;
        const int k0 = it * BK;
#pragma unroll
        for (int h = 0; h < 4; h++) {          // A: 512 chunks (128 rows x 4)
            const int id = tid + h * NTH;
            const int r = id >> 2, cch = id & 3;
            CP16(base + r * 80 + cch * 16,
                 Arow + (size_t)r * lda + k0 + cch * 8);
        }
#pragma unroll
        for (int h = 0; h < 4; h++) {          // B: 512 chunks
            const int id = tid + h * NTH;
            const int r = id >> 2, cch = id & 3;
            CP16(base + A_TILE_BYTES + r * 80 + cch * 16,
                 Bp + (size_t)(bn + r) * ldb + k0 + cch * 8);
        }
        CP_COMMIT();
    };

    float c[4][8][4] = {};

    issue(0);
    issue(1);
    issue(2);

    for (int it = 0; it < kch; ++it) {
        CP_WAIT2();
        __syncthreads();
        if (it + 3 < kch) issue(it + 3);
        else CP_COMMIT();
        const __half* As = (const __half*)(smraw + (it & (STAGES - 1)) * STAGE_BYTES);
        const __half* Bs = As + A_TILE_BYTES / 2;
        mma_stage(As, Bs, wm, wn, lr, lc, c);
    }

    // ---- epilogues ----
    if (EPI == 0) {
        __half* Cp = (__half*)Cbv;
#pragma unroll
        for (int i = 0; i < 4; i++)
#pragma unroll
            for (int j = 0; j < 8; j++) {
                const int r0 = qm + wm + 16 * i + lr;
                const int cc = bn + wn + 8 * j + 2 * lc;
                *(__half2*)&Cp[(size_t)r0 * A_ + cc] =
                    __floats2half2_rn(c[i][j][0], c[i][j][1]);
                *(__half2*)&Cp[(size_t)(r0 + 8) * A_ + cc] =
                    __floats2half2_rn(c[i][j][2], c[i][j][3]);
            }
    } else if (EPI == 1) {
        // transpose through smem, then coalesced writes to Vt[a][s]
        CP_WAIT0();
        __syncthreads();
        __half* smT = (__half*)smraw;          // [n][m], stride 136 halfs
#pragma unroll
        for (int i = 0; i < 4; i++)
#pragma unroll
            for (int j = 0; j < 8; j++) {
                const int m = wm + 16 * i + lr;
                const int n = wn + 8 * j + 2 * lc;
                smT[(n    ) * 136 + m]     = __float2half_rn(c[i][j][0]);
                smT[(n + 1) * 136 + m]     = __float2half_rn(c[i][j][1]);
                smT[(n    ) * 136 + m + 8] = __float2half_rn(c[i][j][2]);
                smT[(n + 1) * 136 + m + 8] = __float2half_rn(c[i][j][3]);
            }
        __syncthreads();
        const int b = qm >> 12, s0 = qm & (S_ - 1);
        __half* Vt = (__half*)Cbv + (size_t)b * A_ * S_ + s0;
        for (int nn = 0; nn < 32; nn++) {
            const int n = warp * 32 + nn;
            uint2 v = *(const uint2*)(smT + n * 136 + lane * 4);
            *(uint2*)(Vt + (size_t)(bn + n) * S_ + lane * 4) = v;
        }
    } else if (EPI == 2) {
        float* Cp = (float*)Cbv + (size_t)bz * S_ * S_;
        const float scale = rsqrtf((float)A_);
#pragma unroll
        for (int i = 0; i < 4; i++)
#pragma unroll
            for (int j = 0; j < 8; j++) {
                const int r0 = qm + wm + 16 * i + lr;
                const int cc = bn + wn + 8 * j + 2 * lc;
                float2 w0, w1;
                w0.x = (cc     <= r0) ? c[i][j][0] * scale : NEG_INF;
                w0.y = (cc + 1 <= r0) ? c[i][j][1] * scale : NEG_INF;
                w1.x = (cc     <= r0 + 8) ? c[i][j][2] * scale : NEG_INF;
                w1.y = (cc + 1 <= r0 + 8) ? c[i][j][3] * scale : NEG_INF;
                *(float2*)&Cp[(size_t)r0 * S_ + cc] = w0;
                *(float2*)&Cp[(size_t)(r0 + 8) * S_ + cc] = w1;
            }
    } else {
        float* Cp = (float*)Cbv + (size_t)bz * S_ * A_;
#pragma unroll
        for (int i = 0; i < 4; i++)
#pragma unroll
            for (int j = 0; j < 8; j++) {
                const int r0 = qm + wm + 16 * i + lr;
                const int cc = bn + wn + 8 * j + 2 * lc;
                *(float2*)&Cp[(size_t)r0 * A_ + cc] =
                    make_float2(rintf(c[i][j][0] * 1e4f) * 1e-4f,
                                rintf(c[i][j][1] * 1e4f) * 1e-4f);
                *(float2*)&Cp[(size_t)(r0 + 8) * A_ + cc] =
                    make_float2(rintf(c[i][j][2] * 1e4f) * 1e-4f,
                                rintf(c[i][j][3] * 1e4f) * 1e-4f);
            }
    }
}

// ---------------------------------------------------------------------------
// prepass: fp32 -> fp16 (rn) conversion, 8 elems/thread
// ---------------------------------------------------------------------------
__global__ void round_h(const float* __restrict__ in, __half* __restrict__ out,
                        int n8) {
    const int i = blockIdx.x * 256 + threadIdx.x;
    if (i < n8) {
        const float4* i4 = (const float4*)in + (size_t)i * 2;
        float4 v0 = i4[0], v1 = i4[1];
        __half2* o2 = (__half2*)(out + (size_t)i * 8);
        o2[0] = __floats2half2_rn(v0.x, v0.y);
        o2[1] = __floats2half2_rn(v0.z, v0.w);
        o2[2] = __floats2half2_rn(v1.x, v1.y);
        o2[3] = __floats2half2_rn(v1.z, v1.w);
    }
}

// ---------------------------------------------------------------------------
// row softmax over the causal prefix (fp32 scores in g_P), probs -> fp16 g_Ph
// ---------------------------------------------------------------------------
__global__ void __launch_bounds__(256)
softmax_kernel() {
    const size_t row = blockIdx.x;
    const int q = (int)(row & (S_ - 1));
    const int klen = (q & ~127) + 128;
    float* __restrict__ p = g_P + row * S_;
    __half* __restrict__ ph = g_Ph + row * S_;
    const int tid = threadIdx.x;
    __shared__ float red[8];

    float m = NEG_INF;
    for (int i = tid; i < klen; i += 256) m = fmaxf(m, p[i]);
#pragma unroll
    for (int o = 16; o > 0; o >>= 1) m = fmaxf(m, __shfl_xor_sync(0xffffffff, m, o));
    if ((tid & 31) == 0) red[tid >> 5] = m;
    __syncthreads();
    if (tid < 32) {
        float v = (tid < 8) ? red[tid] : NEG_INF;
#pragma unroll
        for (int o = 4; o > 0; o >>= 1) v = fmaxf(v, __shfl_xor_sync(0xffffffff, v, o));
        if (tid == 0) red[0] = v;
    }
    __syncthreads();
    const float M = red[0];
    __syncthreads();

    float s = 0.f;
    for (int i = tid; i < klen; i += 256) {
        float e = __expf(p[i] - M);
        p[i] = e;
        s += e;
    }
#pragma unroll
    for (int o = 16; o > 0; o >>= 1) s += __shfl_xor_sync(0xffffffff, s, o);
    if ((tid & 31) == 0) red[tid >> 5] = s;
    __syncthreads();
    if (tid < 32) {
        float v = (tid < 8) ? red[tid] : 0.f;
#pragma unroll
        for (int o = 4; o > 0; o >>= 1) v += __shfl_xor_sync(0xffffffff, v, o);
        if (tid == 0) red[0] = v;
    }
    __syncthreads();
    const float inv = 1.f / red[0];

    for (int i = tid; i < klen; i += 256) ph[i] = __float2half_rn(p[i] * inv);
}

// ---------------------------------------------------------------------------
extern "C" void kernel_launch(void* const* d_in, const int* in_sizes, int n_in,
                              void* d_out, int out_size) {
    const float* x  = (const float*)d_in[0];   // embedded [B,S,E]
    const float* Wk = (const float*)d_in[1];
    const float* Wq = (const float*)d_in[2];
    const float* Wv = (const float*)d_in[3];
    float* out = (float*)d_out;

    __half *dXh, *dWqh, *dWkh, *dWvh, *dQh, *dKh, *dVt, *dPh;
    float *dP;
    cudaGetSymbolAddress((void**)&dXh,  g_Xh);
    cudaGetSymbolAddress((void**)&dWqh, g_Wqh);
    cudaGetSymbolAddress((void**)&dWkh, g_Wkh);
    cudaGetSymbolAddress((void**)&dWvh, g_Wvh);
    cudaGetSymbolAddress((void**)&dQh,  g_Qh);
    cudaGetSymbolAddress((void**)&dKh,  g_Kh);
    cudaGetSymbolAddress((void**)&dVt,  g_Vt);
    cudaGetSymbolAddress((void**)&dP,   g_P);
    cudaGetSymbolAddress((void**)&dPh,  g_Ph);

    cudaFuncSetAttribute(gemm_h<0>, cudaFuncAttributeMaxDynamicSharedMemorySize, SMEM_DYN);
    cudaFuncSetAttribute(gemm_h<1>, cudaFuncAttributeMaxDynamicSharedMemorySize, SMEM_DYN);
    cudaFuncSetAttribute(gemm_h<2>, cudaFuncAttributeMaxDynamicSharedMemorySize, SMEM_DYN);
    cudaFuncSetAttribute(gemm_h<3>, cudaFuncAttributeMaxDynamicSharedMemorySize, SMEM_DYN);

    // prepass: fp32 -> fp16 (11-bit significand, same quantization as tf32)
    const int XN8 = B_ * S_ * E_ / 8;
    const int WN8 = A_ * E_ / 8;
    round_h<<<(XN8 + 255) / 256, 256>>>(x,  dXh,  XN8);
    round_h<<<(WN8 + 255) / 256, 256>>>(Wq, dWqh, WN8);
    round_h<<<(WN8 + 255) / 256, 256>>>(Wk, dWkh, WN8);
    round_h<<<(WN8 + 255) / 256, 256>>>(Wv, dWvh, WN8);

    // projections: M = B*S = 16384, N = A = 2048, K = E = 2048
    dim3 gproj(A_ / TN, (B_ * S_) / TM, 1);
    gemm_h<0><<<gproj, NTH, SMEM_DYN>>>(dXh, dWqh, dQh);
    gemm_h<0><<<gproj, NTH, SMEM_DYN>>>(dXh, dWkh, dKh);
    gemm_h<1><<<gproj, NTH, SMEM_DYN>>>(dXh, dWvh, dVt);

    // scores (causal): triangle-packed grid, 528 tiles per batch
    dim3 gsc(NTILES_TRI, 1, B_);
    gemm_h<2><<<gsc, NTH, SMEM_DYN>>>(dQh, dKh, dP);

    softmax_kernel<<<B_ * S_, 256>>>();

    // P @ V^T (causal K-limit, deepest tiles first), fp32 out rounded to 4 dp
    dim3 gpv(A_ / TN, S_ / TM, B_);
    gemm_h<3><<<gpv, NTH, SMEM_DYN>>>(dPh, dVt, out);
}

// round 12
// speedup vs baseline: 8.4175x; 1.2044x over previous
#include <cuda_runtime.h>
#include <cuda_fp16.h>
#include <math.h>
#include <stdint.h>

// Problem constants
#define B_ 4
#define S_ 4096
#define E_ 2048
#define A_ 2048

// Legacy mma.sync fp16 path (tcgen05 unavailable: harness PTX target is sm_103).
// Measured: GEMMs sit at the legacy HMMA ceiling (~300 TF/s), so this round
// removes FLOPs algebraically: scores = X (Wq^T Wk) X^T  ->  H = Wq^T Wk (tiny),
// Y = X H, scores = Y X^T. Eliminates one full projection (120 GFLOP net).
#define TM 128
#define TN 128
#define BK 32            // halfs per stage-slab (64B rows)
#define STAGES 4
#define NTH 128

#define ASR 40           // smem row stride in halfs (80B)
#define A_TILE_BYTES (TM * ASR * 2)            // 10240
#define B_TILE_BYTES (TN * ASR * 2)            // 10240
#define STAGE_BYTES (A_TILE_BYTES + B_TILE_BYTES)
#define SMEM_DYN (STAGES * STAGE_BYTES)        // 81920

#define NTILES_TRI 528   // 32*33/2 lower-triangle tiles per batch

#define NEG_INF (-1e30f)

// Scratch (allocation-free rule: __device__ globals)
__device__ __half g_Xh [(size_t)B_ * S_ * E_];
__device__ __half g_Wvh[(size_t)A_ * E_];
__device__ __half g_Wqt[(size_t)E_ * A_];       // Wq^T : [e][a]
__device__ __half g_Wkt[(size_t)E_ * A_];       // Wk^T : [e][a]
__device__ __half g_Hh [(size_t)E_ * E_];       // H[e2][e1] = (Wq^T Wk)[e1][e2]
__device__ __half g_Yh [(size_t)B_ * S_ * E_];  // Y = X H
__device__ __half g_Vt [(size_t)B_ * A_ * S_];  // V transposed per batch: [A][S]
__device__ float  g_P  [(size_t)B_ * S_ * S_];  // fp32 scores
__device__ __half g_Ph [(size_t)B_ * S_ * S_];  // fp16 probs

// ---------------------------------------------------------------------------
// helpers
// ---------------------------------------------------------------------------
__device__ __forceinline__ uint32_t s2u(const void* p) {
    uint32_t a;
    asm("{ .reg .u64 t; cvta.to.shared.u64 t, %1; cvt.u32.u64 %0, t; }" : "=r"(a) : "l"(p));
    return a;
}

#define CP16(sm, g) \
    asm volatile("cp.async.cg.shared.global [%0], [%1], 16;" :: "r"(sm), "l"(g) : "memory")
#define CP_COMMIT() asm volatile("cp.async.commit_group;" ::: "memory")
#define CP_WAIT2()  asm volatile("cp.async.wait_group 2;" ::: "memory")
#define CP_WAIT0()  asm volatile("cp.async.wait_group 0;" ::: "memory")

#define MMA_F16(C, Aa, Bb)                                                    \
    asm volatile(                                                             \
        "mma.sync.aligned.m16n8k16.row.col.f32.f16.f16.f32 "                  \
        "{%0,%1,%2,%3}, {%4,%5,%6,%7}, {%8,%9}, {%0,%1,%2,%3};"               \
        : "+f"((C)[0]), "+f"((C)[1]), "+f"((C)[2]), "+f"((C)[3])              \
        : "r"((Aa)[0]), "r"((Aa)[1]), "r"((Aa)[2]), "r"((Aa)[3]),             \
          "r"((Bb)[0]), "r"((Bb)[1]))

// ---------------------------------------------------------------------------
// one BK=32 slab: 2 x k16 substeps, 64x64 warp tile
// ---------------------------------------------------------------------------
__device__ __forceinline__ void mma_stage(const __half* __restrict__ As,
                                          const __half* __restrict__ Bs,
                                          int wm, int wn, int lr, int lc,
                                          float c[4][8][4]) {
#pragma unroll
    for (int kk = 0; kk < BK; kk += 16) {
        uint32_t a[4][4], b[8][2];
#pragma unroll
        for (int i = 0; i < 4; i++) {
            const __half* p = As + (wm + 16 * i + lr) * ASR + kk + 2 * lc;
            a[i][0] = *(const uint32_t*)(p);
            a[i][1] = *(const uint32_t*)(p + 8 * ASR);
            a[i][2] = *(const uint32_t*)(p + 8);
            a[i][3] = *(const uint32_t*)(p + 8 * ASR + 8);
        }
#pragma unroll
        for (int j = 0; j < 8; j++) {
            const __half* p = Bs + (wn + 8 * j + lr) * ASR + kk + 2 * lc;
            b[j][0] = *(const uint32_t*)(p);
            b[j][1] = *(const uint32_t*)(p + 8);
        }
#pragma unroll
        for (int i = 0; i < 4; i++)
#pragma unroll
            for (int j = 0; j < 8; j++) MMA_F16(c[i][j], a[i], b[j]);
    }
}

// ---------------------------------------------------------------------------
// unified fp16 GEMM, all B operands K-major [n][k].
// EPI: 0 = plain -> half row-major (H, Y)
//      1 = proj -> half transposed (Vt[a][s])
//      2 = scores -> fp32 + scale + causal mask (triangle-packed 1D grid)
//      3 = PV -> fp32 rounded to 4 decimals (deepest q-tiles scheduled first)
// ---------------------------------------------------------------------------
template <int EPI>
__global__ void __launch_bounds__(NTH, 2)
gemm_h(const void* __restrict__ Abv, const void* __restrict__ Bbv,
       void* __restrict__ Cbv) {
    const int bz = blockIdx.z;
    int qm, bn;
    if (EPI == 2) {
        // triangular decode: blockIdx.x in [0, 528) -> (qi, ki), ki <= qi
        const int ti = blockIdx.x;
        int qi = (int)((sqrtf(8.f * (float)ti + 1.f) - 1.f) * 0.5f);
        while ((qi + 1) * (qi + 2) / 2 <= ti) qi++;
        while (qi * (qi + 1) / 2 > ti) qi--;
        const int ki = ti - qi * (qi + 1) / 2;
        qm = qi * TM;
        bn = ki * TM;
    } else if (EPI == 3) {
        qm = (int)(gridDim.y - 1 - blockIdx.y) * TM;   // deepest first
        bn = blockIdx.x * TN;
    } else {
        qm = blockIdx.y * TM;
        bn = blockIdx.x * TN;
    }

    const __half* Ap; const __half* Bp;
    int lda, ldb, kch;
    if (EPI <= 1) {
        Ap = (const __half*)Abv; Bp = (const __half*)Bbv;
        lda = E_; ldb = E_; kch = E_ / BK;
    } else if (EPI == 2) {
        Ap = (const __half*)Abv + (size_t)bz * S_ * A_;   // Y rows (per batch)
        Bp = (const __half*)Bbv + (size_t)bz * S_ * E_;   // X rows (per batch)
        lda = A_; ldb = E_; kch = A_ / BK;
    } else {
        Ap = (const __half*)Abv + (size_t)bz * S_ * S_;
        Bp = (const __half*)Bbv + (size_t)bz * A_ * S_;
        lda = S_; ldb = S_; kch = (qm + TM) / BK;   // causal K truncation
    }

    extern __shared__ char smraw[];
    const uint32_t sb = s2u(smraw);
    const int tid = threadIdx.x, lane = tid & 31, warp = tid >> 5;
    const int lr = lane >> 2, lc = lane & 3;
    const int wm = (warp >> 1) * 64, wn = (warp & 1) * 64;

    const __half* Arow = Ap + (size_t)qm * lda;

    // ---- async loaders: 8 x 16B per thread per stage ----
    auto issue = [&](int it) {
        const uint32_t base = sb + (it & (STAGES - 1)) * STAGE_BYTES;
        const int k0 = it * BK;
#pragma unroll
        for (int h = 0; h < 4; h++) {          // A: 512 chunks (128 rows x 4)
            const int id = tid + h * NTH;
            const int r = id >> 2, cch = id & 3;
            CP16(base + r * 80 + cch * 16,
                 Arow + (size_t)r * lda + k0 + cch * 8);
        }
#pragma unroll
        for (int h = 0; h < 4; h++) {          // B: 512 chunks
            const int id = tid + h * NTH;
            const int r = id >> 2, cch = id & 3;
            CP16(base + A_TILE_BYTES + r * 80 + cch * 16,
                 Bp + (size_t)(bn + r) * ldb + k0 + cch * 8);
        }
        CP_COMMIT();
    };

    float c[4][8][4] = {};

    issue(0);
    issue(1);
    issue(2);

    for (int it = 0; it < kch; ++it) {
        CP_WAIT2();
        __syncthreads();
        if (it + 3 < kch) issue(it + 3);
        else CP_COMMIT();
        const __half* As = (const __half*)(smraw + (it & (STAGES - 1)) * STAGE_BYTES);
        const __half* Bs = As + A_TILE_BYTES / 2;
        mma_stage(As, Bs, wm, wn, lr, lc, c);
    }

    // ---- epilogues ----
    if (EPI == 0) {
        __half* Cp = (__half*)Cbv;
#pragma unroll
        for (int i = 0; i < 4; i++)
#pragma unroll
            for (int j = 0; j < 8; j++) {
                const int r0 = qm + wm + 16 * i + lr;
                const int cc = bn + wn + 8 * j + 2 * lc;
                *(__half2*)&Cp[(size_t)r0 * A_ + cc] =
                    __floats2half2_rn(c[i][j][0], c[i][j][1]);
                *(__half2*)&Cp[(size_t)(r0 + 8) * A_ + cc] =
                    __floats2half2_rn(c[i][j][2], c[i][j][3]);
            }
    } else if (EPI == 1) {
        // transpose through smem, then coalesced writes to Vt[a][s]
        CP_WAIT0();
        __syncthreads();
        __half* smT = (__half*)smraw;          // [n][m], stride 136 halfs
#pragma unroll
        for (int i = 0; i < 4; i++)
#pragma unroll
            for (int j = 0; j < 8; j++) {
                const int m = wm + 16 * i + lr;
                const int n = wn + 8 * j + 2 * lc;
                smT[(n    ) * 136 + m]     = __float2half_rn(c[i][j][0]);
                smT[(n + 1) * 136 + m]     = __float2half_rn(c[i][j][1]);
                smT[(n    ) * 136 + m + 8] = __float2half_rn(c[i][j][2]);
                smT[(n + 1) * 136 + m + 8] = __float2half_rn(c[i][j][3]);
            }
        __syncthreads();
        const int b = qm >> 12, s0 = qm & (S_ - 1);
        __half* Vt = (__half*)Cbv + (size_t)b * A_ * S_ + s0;
        for (int nn = 0; nn < 32; nn++) {
            const int n = warp * 32 + nn;
            uint2 v = *(const uint2*)(smT + n * 136 + lane * 4);
            *(uint2*)(Vt + (size_t)(bn + n) * S_ + lane * 4) = v;
        }
    } else if (EPI == 2) {
        float* Cp = (float*)Cbv + (size_t)bz * S_ * S_;
        const float scale = rsqrtf((float)A_);
#pragma unroll
        for (int i = 0; i < 4; i++)
#pragma unroll
            for (int j = 0; j < 8; j++) {
                const int r0 = qm + wm + 16 * i + lr;
                const int cc = bn + wn + 8 * j + 2 * lc;
                float2 w0, w1;
                w0.x = (cc     <= r0) ? c[i][j][0] * scale : NEG_INF;
                w0.y = (cc + 1 <= r0) ? c[i][j][1] * scale : NEG_INF;
                w1.x = (cc     <= r0 + 8) ? c[i][j][2] * scale : NEG_INF;
                w1.y = (cc + 1 <= r0 + 8) ? c[i][j][3] * scale : NEG_INF;
                *(float2*)&Cp[(size_t)r0 * S_ + cc] = w0;
                *(float2*)&Cp[(size_t)(r0 + 8) * S_ + cc] = w1;
            }
    } else {
        float* Cp = (float*)Cbv + (size_t)bz * S_ * A_;
#pragma unroll
        for (int i = 0; i < 4; i++)
#pragma unroll
            for (int j = 0; j < 8; j++) {
                const int r0 = qm + wm + 16 * i + lr;
                const int cc = bn + wn + 8 * j + 2 * lc;
                *(float2*)&Cp[(size_t)r0 * A_ + cc] =
                    make_float2(rintf(c[i][j][0] * 1e4f) * 1e-4f,
                                rintf(c[i][j][1] * 1e4f) * 1e-4f);
                *(float2*)&Cp[(size_t)(r0 + 8) * A_ + cc] =
                    make_float2(rintf(c[i][j][2] * 1e4f) * 1e-4f,
                                rintf(c[i][j][3] * 1e4f) * 1e-4f);
            }
    }
}

// ---------------------------------------------------------------------------
// prepass: fp32 -> fp16 (rn) conversion, 8 elems/thread
// ---------------------------------------------------------------------------
__global__ void round_h(const float* __restrict__ in, __half* __restrict__ out,
                        int n8) {
    const int i = blockIdx.x * 256 + threadIdx.x;
    if (i < n8) {
        const float4* i4 = (const float4*)in + (size_t)i * 2;
        float4 v0 = i4[0], v1 = i4[1];
        __half2* o2 = (__half2*)(out + (size_t)i * 8);
        o2[0] = __floats2half2_rn(v0.x, v0.y);
        o2[1] = __floats2half2_rn(v0.z, v0.w);
        o2[2] = __floats2half2_rn(v1.x, v1.y);
        o2[3] = __floats2half2_rn(v1.z, v1.w);
    }
}

// ---------------------------------------------------------------------------
// fused fp32->fp16 + transpose: out[e][a] = (half)in[a][e], 2048x2048
// ---------------------------------------------------------------------------
__global__ void __launch_bounds__(256)
transpose_wh(const float* __restrict__ in, __half* __restrict__ out) {
    __shared__ __half t[32][33];
    const int bx = blockIdx.x * 32, by = blockIdx.y * 32;
    const int x = threadIdx.x & 31, y0 = threadIdx.x >> 5;   // 32 x 8
#pragma unroll
    for (int yy = y0; yy < 32; yy += 8)
        t[yy][x] = __float2half_rn(in[(size_t)(by + yy) * E_ + bx + x]);
    __syncthreads();
#pragma unroll
    for (int yy = y0; yy < 32; yy += 8)
        out[(size_t)(bx + yy) * A_ + by + x] = t[x][yy];
}

// ---------------------------------------------------------------------------
// row softmax over the causal prefix, single pass (16-register row cache):
// one fp32 read, one fp16 write.
// ---------------------------------------------------------------------------
__global__ void __launch_bounds__(256)
softmax_kernel() {
    const size_t row = blockIdx.x;
    const int q = (int)(row & (S_ - 1));
    const int klen = (q & ~127) + 128;
    const float* __restrict__ p = g_P + row * S_;
    __half* __restrict__ ph = g_Ph + row * S_;
    const int tid = threadIdx.x;
    __shared__ float red[8];

    float v[16];
    float m = NEG_INF;
#pragma unroll
    for (int t = 0; t < 16; t++) {
        const int i = t * 256 + tid;
        v[t] = (i < klen) ? p[i] : NEG_INF;
        m = fmaxf(m, v[t]);
    }
#pragma unroll
    for (int o = 16; o > 0; o >>= 1) m = fmaxf(m, __shfl_xor_sync(0xffffffff, m, o));
    if ((tid & 31) == 0) red[tid >> 5] = m;
    __syncthreads();
    if (tid < 32) {
        float w = (tid < 8) ? red[tid] : NEG_INF;
#pragma unroll
        for (int o = 4; o > 0; o >>= 1) w = fmaxf(w, __shfl_xor_sync(0xffffffff, w, o));
        if (tid == 0) red[0] = w;
    }
    __syncthreads();
    const float M = red[0];
    __syncthreads();

    float s = 0.f;
#pragma unroll
    for (int t = 0; t < 16; t++) {
        const float e = __expf(v[t] - M);   // v=NEG_INF -> 0, no masking needed
        v[t] = e;
        s += e;
    }
#pragma unroll
    for (int o = 16; o > 0; o >>= 1) s += __shfl_xor_sync(0xffffffff, s, o);
    if ((tid & 31) == 0) red[tid >> 5] = s;
    __syncthreads();
    if (tid < 32) {
        float w = (tid < 8) ? red[tid] : 0.f;
#pragma unroll
        for (int o = 4; o > 0; o >>= 1) w += __shfl_xor_sync(0xffffffff, w, o);
        if (tid == 0) red[0] = w;
    }
    __syncthreads();
    const float inv = 1.f / red[0];

#pragma unroll
    for (int t = 0; t < 16; t++) {
        const int i = t * 256 + tid;
        if (i < klen) ph[i] = __float2half_rn(v[t] * inv);
    }
}

// ---------------------------------------------------------------------------
extern "C" void kernel_launch(void* const* d_in, const int* in_sizes, int n_in,
                              void* d_out, int out_size) {
    const float* x  = (const float*)d_in[0];   // embedded [B,S,E]
    const float* Wk = (const float*)d_in[1];
    const float* Wq = (const float*)d_in[2];
    const float* Wv = (const float*)d_in[3];
    float* out = (float*)d_out;

    __half *dXh, *dWvh, *dWqt, *dWkt, *dHh, *dYh, *dVt, *dPh;
    float *dP;
    cudaGetSymbolAddress((void**)&dXh,  g_Xh);
    cudaGetSymbolAddress((void**)&dWvh, g_Wvh);
    cudaGetSymbolAddress((void**)&dWqt, g_Wqt);
    cudaGetSymbolAddress((void**)&dWkt, g_Wkt);
    cudaGetSymbolAddress((void**)&dHh,  g_Hh);
    cudaGetSymbolAddress((void**)&dYh,  g_Yh);
    cudaGetSymbolAddress((void**)&dVt,  g_Vt);
    cudaGetSymbolAddress((void**)&dP,   g_P);
    cudaGetSymbolAddress((void**)&dPh,  g_Ph);

    cudaFuncSetAttribute(gemm_h<0>, cudaFuncAttributeMaxDynamicSharedMemorySize, SMEM_DYN);
    cudaFuncSetAttribute(gemm_h<1>, cudaFuncAttributeMaxDynamicSharedMemorySize, SMEM_DYN);
    cudaFuncSetAttribute(gemm_h<2>, cudaFuncAttributeMaxDynamicSharedMemorySize, SMEM_DYN);
    cudaFuncSetAttribute(gemm_h<3>, cudaFuncAttributeMaxDynamicSharedMemorySize, SMEM_DYN);

    // prepass: X and Wv -> fp16; Wq, Wk -> fp16 transposed [e][a]
    const int XN8 = B_ * S_ * E_ / 8;
    const int WN8 = A_ * E_ / 8;
    round_h<<<(XN8 + 255) / 256, 256>>>(x,  dXh,  XN8);
    round_h<<<(WN8 + 255) / 256, 256>>>(Wv, dWvh, WN8);
    dim3 gtr(E_ / 32, A_ / 32);
    transpose_wh<<<gtr, 256>>>(Wq, dWqt);
    transpose_wh<<<gtr, 256>>>(Wk, dWkt);

    // H[e2][e1] = sum_a Wkt[e2,a] * Wqt[e1,a] = (Wq^T Wk)[e1][e2]
    dim3 gH(E_ / TN, E_ / TM, 1);
    gemm_h<0><<<gH, NTH, SMEM_DYN>>>(dWkt, dWqt, dHh);

    // Y = X H : M = B*S = 16384, N = E = 2048, K = E (B operand = H[n][k])
    dim3 gY(E_ / TN, (B_ * S_) / TM, 1);
    gemm_h<0><<<gY, NTH, SMEM_DYN>>>(dXh, dHh, dYh);

    // V projection -> transposed Vt
    dim3 gproj(A_ / TN, (B_ * S_) / TM, 1);
    gemm_h<1><<<gproj, NTH, SMEM_DYN>>>(dXh, dWvh, dVt);

    // scores = Y X^T (causal): triangle-packed grid, 528 tiles per batch
    dim3 gsc(NTILES_TRI, 1, B_);
    gemm_h<2><<<gsc, NTH, SMEM_DYN>>>(dYh, dXh, dP);

    softmax_kernel<<<B_ * S_, 256>>>();

    // P @ V^T (causal K-limit, deepest tiles first), fp32 out rounded to 4 dp
    dim3 gpv(A_ / TN, S_ / TM, B_);
    gemm_h<3><<<gpv, NTH, SMEM_DYN>>>(dPh, dVt, out);
}